// round 4
// baseline (speedup 1.0000x reference)
#include <cuda_runtime.h>
#include <stdint.h>

// Problem constants
#define HWp   65536      // 256*256
#define Bp    2
#define Jp    512
#define JJp   (Jp*Jp)    // 262144
#define CAPp  16384      // candidate capacity per batch (expected ~7.3k)
#define THp   0.008f
#define J2Lp  10.0f
#define SCALEp 5.0f
#define NBINS 4096       // histogram bins over key top-12 bits
#define SELC  2048       // compaction capacity (>= 512 + max bin pop)
#define RADp  3.16227766f // sqrt(10): max distance that can ever match
#define ZERO4 ((Bp*JJp*5)/4)  // float4 count of counts+support region
#define ZBLK  1280            // zeroing blocks per batch row (2*1280*256 == ZERO4)

// Scratch (static device globals — no allocation allowed)
__device__ unsigned long long  g_ckey[Bp][CAPp];
__device__ int                 g_ccnt[Bp];        // zero-init; reset by k_adj tail
__device__ int                 g_nvalid[Bp];
__device__ float2              g_juncs[Bp][Jp];
__device__ int                 g_cellStart[Bp][1025];  // CSR over 32x32 cells of 8px
__device__ float2              g_gpos[Bp][Jp];         // junction pos in cell order
__device__ int                 g_gidx[Bp][Jp];         // original top-k index

__device__ __forceinline__ float sigf(float x) { return 1.0f / (1.0f + expf(-x)); }

// ---------------------------------------------------------------------------
// K1: fused softmax-prob + 3x3 NMS + candidate append (smem halo tile),
// plus zeroing of the counts+support output region (extra blocks).
// prob = softmax(raw[:,5:7],axis=1)[:,1], max-subtract form (bit-identical
// to the previously passing two-kernel version).
// key = (~float_bits(score) << 32) | pixel -> ascending == score desc,
// pixel-index asc on ties (matches jax.lax.top_k ordering).
// ---------------------------------------------------------------------------
__global__ void __launch_bounds__(256) k_cand_zero(const float* __restrict__ raw,
                                                   float4* __restrict__ zdst) {
    int b = blockIdx.y;
    if (blockIdx.x >= 256) {                       // zeroing blocks
        int zi = ((blockIdx.x - 256) + b * ZBLK) * 256 + threadIdx.x;
        if (zi < ZERO4) zdst[zi] = make_float4(0.f, 0.f, 0.f, 0.f);
        return;
    }
    __shared__ float sp[18 * 18];                  // 16x16 tile + 1px halo
    int tile = blockIdx.x;
    int tx0 = (tile & 15) << 4;
    int ty0 = (tile >> 4) << 4;
    const float* r5p = raw + (size_t)b * 9 * HWp + 5 * HWp;
    const float* r6p = raw + (size_t)b * 9 * HWp + 6 * HWp;

    for (int i = threadIdx.x; i < 324; i += 256) {
        int hx = tx0 - 1 + (i % 18);
        int hy = ty0 - 1 + (i / 18);
        float v = -1.0f;                           // OOB: below any prob (>0)
        if ((unsigned)hx < 256u && (unsigned)hy < 256u) {
            int p = (hy << 8) + hx;
            float r5 = r5p[p];
            float r6 = r6p[p];
            float m  = fmaxf(r5, r6);
            float e5 = expf(r5 - m);
            float e6 = expf(r6 - m);
            v = e6 / (e5 + e6);
        }
        sp[i] = v;
    }
    __syncthreads();

    int lx = (threadIdx.x & 15) + 1;
    int ly = (threadIdx.x >> 4) + 1;
    float a = sp[ly * 18 + lx];
    if (a <= THp) return;
    int c = ly * 18 + lx;
    float mx;
    mx = fmaxf(sp[c - 19], sp[c - 18]);
    mx = fmaxf(mx, sp[c - 17]);
    mx = fmaxf(mx, sp[c - 1]);
    mx = fmaxf(mx, sp[c + 1]);
    mx = fmaxf(mx, sp[c + 17]);
    mx = fmaxf(mx, sp[c + 18]);
    mx = fmaxf(mx, sp[c + 19]);
    if (a >= mx) {                                 // a == maxpool(a) semantics
        int p = ((ty0 + ly - 1) << 8) + (tx0 + lx - 1);
        int pos = atomicAdd(&g_ccnt[b], 1);
        if (pos < CAPp) {
            unsigned inv = ~__float_as_uint(a);
            g_ckey[b][pos] = (((unsigned long long)inv) << 32) | (unsigned)p;
        }
    }
}

// ---------------------------------------------------------------------------
// K2: histogram-select the <=SELC smallest-key superset, rank each selected
// key by counting (exact order, zero barriers), decode junctions, build the
// CSR spatial grid. One block per batch.
// ---------------------------------------------------------------------------
struct SmemT {
    union {
        int hist[NBINS];                 // phase 1: histogram/scan
        int cnt1[1024];                  // phase 2: cell counts / cursors
    } u;
    unsigned long long sel[SELC];
    float2 jsm[Jp];
    int warpsum[32];
    int sT, sCum, sSel;
};

__global__ void __launch_bounds__(1024) k_topk(const float* __restrict__ raw) {
    __shared__ SmemT sm;
    int b = blockIdx.x;
    int tid = threadIdx.x;
    int lane = tid & 31, wid = tid >> 5;
    int cnt = min(g_ccnt[b], CAPp);
    int target = min(Jp, cnt);

    if (cnt == 0) {   // defensive; never hit with this data
        if (tid < Jp) g_juncs[b][tid] = make_float2(0.f, 0.f);
        if (tid <= 1024) g_cellStart[b][tid] = 0;
        if (tid == 0) g_nvalid[b] = 0;
        return;
    }

    // --- histogram over key top-12 bits ---
    for (int i = tid; i < NBINS; i += 1024) sm.u.hist[i] = 0;
    __syncthreads();
    for (int i = tid; i < cnt; i += 1024)
        atomicAdd(&sm.u.hist[(int)(g_ckey[b][i] >> 52)], 1);
    __syncthreads();

    // --- block scan (4 bins/thread) to find threshold bin T ---
    int base = tid * 4;
    int h0 = sm.u.hist[base], h1 = sm.u.hist[base+1];
    int h2 = sm.u.hist[base+2], h3 = sm.u.hist[base+3];
    int tot = h0 + h1 + h2 + h3;
    int inc = tot;
    #pragma unroll
    for (int d = 1; d < 32; d <<= 1) {
        int n = __shfl_up_sync(0xffffffffu, inc, d);
        if (lane >= d) inc += n;
    }
    if (lane == 31) sm.warpsum[wid] = inc;
    __syncthreads();
    if (wid == 0) {
        int v = sm.warpsum[lane];
        int i2 = v;
        #pragma unroll
        for (int d = 1; d < 32; d <<= 1) {
            int n = __shfl_up_sync(0xffffffffu, i2, d);
            if (lane >= d) i2 += n;
        }
        sm.warpsum[lane] = i2 - v;   // exclusive warp offsets
    }
    if (tid == 0) sm.sSel = 0;
    __syncthreads();
    {
        int run = sm.warpsum[wid] + inc - tot;   // exclusive prefix for this thread
        int hh[4] = {h0, h1, h2, h3};
        #pragma unroll
        for (int i = 0; i < 4; i++) {
            run += hh[i];
            if (run >= target && run - hh[i] < target) { sm.sT = base + i; sm.sCum = run; }
        }
    }
    __syncthreads();
    int T = sm.sT;
    int S = min(sm.sCum, SELC);

    // --- compact keys with bin <= T (superset of the `target` smallest) ---
    for (int i = tid; i < cnt; i += 1024) {
        unsigned long long key = g_ckey[b][i];
        if ((int)(key >> 52) <= T) {
            int pos = atomicAdd(&sm.sSel, 1);
            if (pos < SELC) sm.sel[pos] = key;
        }
    }
    if (tid < Jp) sm.jsm[tid] = make_float2(0.f, 0.f);
    __syncthreads();

    int nv = target;
    if (tid == 0) g_nvalid[b] = nv;

    // --- rank-by-count: rank r = #(keys < mine). Keys unique -> exact order,
    //     identical to a full ascending sort; no barriers needed inside. ---
    const float* rb = raw + (size_t)b * 9 * HWp;
    for (int t = tid; t < S; t += 1024) {
        unsigned long long key = sm.sel[t];
        int r = 0;
        for (int i = 0; i < S; i++) r += (sm.sel[i] < key);
        if (r < nv) {
            int p = (int)(key & 0xFFFFFFFFu);
            float offx = sigf(rb[7 * HWp + p]) - 0.5f;
            float offy = sigf(rb[8 * HWp + p]) - 0.5f;
            float qx = (float)(p & 255) + offx + 0.5f;
            float qy = (float)(p >> 8) + offy + 0.5f;
            sm.jsm[r] = make_float2(qx, qy);
        }
    }
    __syncthreads();

    // --- publish junctions; compute this thread's cell ---
    float qx = 0.f, qy = 0.f;
    int myCell = -1;
    if (tid < Jp) {
        float2 q = sm.jsm[tid];
        qx = q.x; qy = q.y;
        g_juncs[b][tid] = q;
        if (tid < nv) myCell = (((int)qy >> 3) << 5) + ((int)qx >> 3); // 32x32 cells, 8px
    }
    __syncthreads();          // done with hist region before reuse

    // --- build CSR cell grid ---
    sm.u.cnt1[tid] = 0;
    __syncthreads();
    if (myCell >= 0) atomicAdd(&sm.u.cnt1[myCell], 1);
    __syncthreads();
    int v = sm.u.cnt1[tid];
    int inc2 = v;
    #pragma unroll
    for (int d = 1; d < 32; d <<= 1) {
        int n = __shfl_up_sync(0xffffffffu, inc2, d);
        if (lane >= d) inc2 += n;
    }
    if (lane == 31) sm.warpsum[wid] = inc2;
    __syncthreads();
    if (wid == 0) {
        int vv = sm.warpsum[lane];
        int i2 = vv;
        #pragma unroll
        for (int d = 1; d < 32; d <<= 1) {
            int n = __shfl_up_sync(0xffffffffu, i2, d);
            if (lane >= d) i2 += n;
        }
        sm.warpsum[lane] = i2 - vv;
    }
    __syncthreads();
    int excl = sm.warpsum[wid] + inc2 - v;
    g_cellStart[b][tid] = excl;
    if (tid == 1023) g_cellStart[b][1024] = excl + v;   // == nv
    __syncthreads();
    sm.u.cnt1[tid] = excl;     // fill cursors
    __syncthreads();
    if (myCell >= 0) {
        int pos = atomicAdd(&sm.u.cnt1[myCell], 1);
        g_gpos[b][pos] = make_float2(qx, qy);
        g_gidx[b][pos] = tid;
    }
}

// ---------------------------------------------------------------------------
// Pruned nearest-junction search: any junction with d^2 < 10 lies within the
// cell window [e-sqrt(10), e+sqrt(10)]. (d, idx) lexicographic min reproduces
// the reference argmin first-index tie-break exactly.
// ---------------------------------------------------------------------------
__device__ __forceinline__ void nearest(int b, float ex, float ey,
                                        float& bd, int& bi) {
    int cx0 = ((int)fmaxf(ex - RADp, 0.0f)) >> 3;
    int cx1 = ((int)fminf(ex + RADp, 255.0f)) >> 3;
    int cy0 = ((int)fmaxf(ey - RADp, 0.0f)) >> 3;
    int cy1 = ((int)fminf(ey + RADp, 255.0f)) >> 3;
    for (int cy = cy0; cy <= cy1; cy++) {
        for (int cx = cx0; cx <= cx1; cx++) {
            int c = (cy << 5) + cx;
            int s = __ldg(&g_cellStart[b][c]);
            int e = __ldg(&g_cellStart[b][c + 1]);
            for (int k = s; k < e; k++) {
                float2 q = __ldg(&g_gpos[b][k]);
                int idx  = __ldg(&g_gidx[b][k]);
                float dx = ex - q.x, dy = ey - q.y;
                float d = fmaf(dy, dy, dx * dx);
                if (d < bd || (d == bd && idx < bi)) { bd = d; bi = idx; }
            }
        }
    }
}

// ---------------------------------------------------------------------------
// Per-pixel line decode + endpoint match + scatter (called twice per thread).
// ---------------------------------------------------------------------------
__device__ __forceinline__ void decode_match(int b, int p,
                                             const float* __restrict__ rb,
                                             float* __restrict__ counts,
                                             float* __restrict__ support) {
    float r0 = rb[p];
    float r1 = rb[HWp + p];
    float r2 = rb[2 * HWp + p];
    float r3 = rb[3 * HWp + p];

    float md0 = sigf(r0), md1 = sigf(r1), md2 = sigf(r2);
    float d   = sigf(r3);
    float theta = (md0 - 0.5f) * 6.28318530717958647692f;
    float cs = cosf(theta), ss = sinf(theta);
    float yst = tanf(md1 * 1.57079632679489661923f);
    float yed = tanf(-md2 * 1.57079632679489661923f);
    float ds = d * SCALEp;
    float x0 = (float)(p & 255);
    float y0 = (float)(p >> 8);
    float l0 = fminf(fmaxf((cs - ss * yst) * ds + x0, 0.0f), 255.0f);
    float l1 = fminf(fmaxf((ss + cs * yst) * ds + y0, 0.0f), 255.0f);
    float l2 = fminf(fmaxf((cs - ss * yed) * ds + x0, 0.0f), 255.0f);
    float l3 = fminf(fmaxf((ss + cs * yed) * ds + y0, 0.0f), 255.0f);

    float bd1 = 1e30f, bd2 = 1e30f;
    int   bi1 = Jp,    bi2 = Jp;
    nearest(b, l0, l1, bd1, bi1);
    nearest(b, l2, l3, bd2, bi2);

    if (bd1 < J2Lp && bd2 < J2Lp && bi1 != bi2) {
        int imin = min(bi1, bi2), imax = max(bi1, bi2);
        int g = b * JJp + imin * Jp + imax;
        atomicAdd(&counts[g], 1.0f);
        atomicAdd(&support[(size_t)g * 4 + 0], l0);
        atomicAdd(&support[(size_t)g * 4 + 1], l1);
        atomicAdd(&support[(size_t)g * 4 + 2], l2);
        atomicAdd(&support[(size_t)g * 4 + 3], l3);
    }
}

__global__ void __launch_bounds__(256) k_match(const float* __restrict__ raw,
                                               float* __restrict__ counts,
                                               float* __restrict__ support) {
    int b = blockIdx.y;
    const float* rb = raw + (size_t)b * 9 * HWp;
    int base = blockIdx.x * 512 + threadIdx.x;
    decode_match(b, base,       rb, counts, support);
    decode_match(b, base + 256, rb, counts, support);
}

// ---------------------------------------------------------------------------
// K4: lines_adj = (junc[i], junc[j]) masked by counts>0; writes every entry.
// Also resets candidate counters for the next graph replay.
// ---------------------------------------------------------------------------
__global__ void k_adj(const float* __restrict__ counts, float4* __restrict__ out) {
    int pid = blockIdx.x * blockDim.x + threadIdx.x;   // 0 .. Bp*JJp-1
    if (pid == 0) { g_ccnt[0] = 0; g_ccnt[1] = 0; }
    int b = pid >> 18;                                  // JJp = 2^18
    int q = pid & (JJp - 1);
    float c = counts[pid];
    float4 v = make_float4(0.f, 0.f, 0.f, 0.f);
    if (c > 0.0f) {
        float2 A  = g_juncs[b][q >> 9];
        float2 Bq = g_juncs[b][q & (Jp - 1)];
        v = make_float4(A.x, A.y, Bq.x, Bq.y);
    }
    out[pid] = v;
}

// ---------------------------------------------------------------------------
// Launch. Output layout: lines_adj [B*JJ*4] | counts [B*JJ] | support [B*JJ*4]
// ---------------------------------------------------------------------------
extern "C" void kernel_launch(void* const* d_in, const int* in_sizes, int n_in,
                              void* d_out, int out_size) {
    const float* raw = (const float*)d_in[0];
    float* out = (float*)d_out;
    float* counts  = out + (size_t)Bp * JJp * 4;
    float* support = counts + (size_t)Bp * JJp;

    dim3 gcand(256 + ZBLK, Bp);
    k_cand_zero<<<gcand, 256>>>(raw, (float4*)counts);
    k_topk<<<Bp, 1024>>>(raw);
    dim3 gmatch(HWp / 512, Bp);
    k_match<<<gmatch, 256>>>(raw, counts, support);
    k_adj<<<(Bp * JJp) / 256, 256>>>(counts, (float4*)out);
}

// round 5
// speedup vs baseline: 2.6492x; 2.6492x over previous
#include <cuda_runtime.h>
#include <stdint.h>

// Problem constants
#define HWp   65536      // 256*256
#define Bp    2
#define Jp    512
#define JJp   (Jp*Jp)    // 262144
#define CAPp  16384      // candidate capacity per batch (expected ~7.3k)
#define THp   0.008f
#define J2Lp  10.0f
#define SCALEp 5.0f
#define NBINS 4096       // histogram bins (12 bits per level)
#define SELC  1024       // compaction capacity (S ~= 515 after 2-level select)
#define RADp  3.16227766f // sqrt(10): max distance that can ever match
#define ZERO4 ((Bp*JJp*5)/4)  // float4 count of counts+support region
#define ZBLK  1280            // zeroing blocks per batch row (2*1280*256 == ZERO4)

// Scratch (static device globals — no allocation allowed)
__device__ unsigned long long  g_ckey[Bp][CAPp];
__device__ int                 g_ccnt[Bp];        // zero-init; reset by k_adj tail
__device__ int                 g_nvalid[Bp];
__device__ float2              g_juncs[Bp][Jp];
__device__ int                 g_cellStart[Bp][1025];  // CSR over 32x32 cells of 8px
__device__ float2              g_gpos[Bp][Jp];         // junction pos in cell order
__device__ int                 g_gidx[Bp][Jp];         // original top-k index

__device__ __forceinline__ float sigf(float x) { return 1.0f / (1.0f + expf(-x)); }

// ---------------------------------------------------------------------------
// K1: fused softmax-prob + 3x3 NMS + candidate append (smem halo tile),
// plus zeroing of the counts+support output region (extra blocks).
// key = (~float_bits(score) << 32) | pixel -> ascending == score desc,
// pixel-index asc on ties (matches jax.lax.top_k ordering).
// ---------------------------------------------------------------------------
__global__ void __launch_bounds__(256) k_cand_zero(const float* __restrict__ raw,
                                                   float4* __restrict__ zdst) {
    int b = blockIdx.y;
    if (blockIdx.x >= 256) {                       // zeroing blocks
        int zi = ((blockIdx.x - 256) + b * ZBLK) * 256 + threadIdx.x;
        if (zi < ZERO4) zdst[zi] = make_float4(0.f, 0.f, 0.f, 0.f);
        return;
    }
    __shared__ float sp[18 * 18];                  // 16x16 tile + 1px halo
    int tile = blockIdx.x;
    int tx0 = (tile & 15) << 4;
    int ty0 = (tile >> 4) << 4;
    const float* r5p = raw + (size_t)b * 9 * HWp + 5 * HWp;
    const float* r6p = raw + (size_t)b * 9 * HWp + 6 * HWp;

    for (int i = threadIdx.x; i < 324; i += 256) {
        int hx = tx0 - 1 + (i % 18);
        int hy = ty0 - 1 + (i / 18);
        float v = -1.0f;                           // OOB: below any prob (>0)
        if ((unsigned)hx < 256u && (unsigned)hy < 256u) {
            int p = (hy << 8) + hx;
            float r5 = r5p[p];
            float r6 = r6p[p];
            float m  = fmaxf(r5, r6);
            float e5 = expf(r5 - m);
            float e6 = expf(r6 - m);
            v = e6 / (e5 + e6);
        }
        sp[i] = v;
    }
    __syncthreads();

    int lx = (threadIdx.x & 15) + 1;
    int ly = (threadIdx.x >> 4) + 1;
    float a = sp[ly * 18 + lx];
    if (a <= THp) return;
    int c = ly * 18 + lx;
    float mx;
    mx = fmaxf(sp[c - 19], sp[c - 18]);
    mx = fmaxf(mx, sp[c - 17]);
    mx = fmaxf(mx, sp[c - 1]);
    mx = fmaxf(mx, sp[c + 1]);
    mx = fmaxf(mx, sp[c + 17]);
    mx = fmaxf(mx, sp[c + 18]);
    mx = fmaxf(mx, sp[c + 19]);
    if (a >= mx) {                                 // a == maxpool(a) semantics
        int p = ((ty0 + ly - 1) << 8) + (tx0 + lx - 1);
        int pos = atomicAdd(&g_ccnt[b], 1);
        if (pos < CAPp) {
            unsigned inv = ~__float_as_uint(a);
            g_ckey[b][pos] = (((unsigned long long)inv) << 32) | (unsigned)p;
        }
    }
}

// ---------------------------------------------------------------------------
// K2: two-level radix select of the top-`target` keys, bitonic sort of the
// small selected superset, junction decode, CSR spatial grid build.
// One block of 1024 threads per batch.
// ---------------------------------------------------------------------------
struct SmemT {
    union {
        int hist[NBINS];                 // histogram (both levels) / scan
        int cnt1[1024];                  // cell counts, then fill cursors
    } u;
    unsigned long long sel[SELC];
    int warpsum[32];
    int sT, sCum, sSel;
};

// Find smallest bin T with cumulative >= target over sm.u.hist (4 bins/thread).
// Writes sm.sT (bin) and sm.sCum (inclusive cumulative through T).
// Caller must __syncthreads() before reading sm.sT / sm.sCum.
__device__ __forceinline__ void scan_find_bin(SmemT& sm, int target,
                                              int tid, int lane, int wid) {
    int base = tid * 4;
    int h0 = sm.u.hist[base], h1 = sm.u.hist[base+1];
    int h2 = sm.u.hist[base+2], h3 = sm.u.hist[base+3];
    int tot = h0 + h1 + h2 + h3;
    int inc = tot;
    #pragma unroll
    for (int d = 1; d < 32; d <<= 1) {
        int n = __shfl_up_sync(0xffffffffu, inc, d);
        if (lane >= d) inc += n;
    }
    if (lane == 31) sm.warpsum[wid] = inc;
    __syncthreads();
    if (wid == 0) {
        int v = sm.warpsum[lane];
        int i2 = v;
        #pragma unroll
        for (int d = 1; d < 32; d <<= 1) {
            int n = __shfl_up_sync(0xffffffffu, i2, d);
            if (lane >= d) i2 += n;
        }
        sm.warpsum[lane] = i2 - v;   // exclusive warp offsets
    }
    __syncthreads();
    int run = sm.warpsum[wid] + inc - tot;   // exclusive prefix for this thread
    int hh[4] = {h0, h1, h2, h3};
    #pragma unroll
    for (int i = 0; i < 4; i++) {
        run += hh[i];
        if (run >= target && run - hh[i] < target) { sm.sT = base + i; sm.sCum = run; }
    }
}

__global__ void __launch_bounds__(1024) k_topk(const float* __restrict__ raw) {
    __shared__ SmemT sm;
    int b = blockIdx.x;
    int tid = threadIdx.x;
    int lane = tid & 31, wid = tid >> 5;
    int cnt = min(g_ccnt[b], CAPp);
    int target = min(Jp, cnt);

    if (cnt == 0) {   // defensive; never hit with this data
        if (tid < Jp) g_juncs[b][tid] = make_float2(0.f, 0.f);
        if (tid <= 1024) g_cellStart[b][tid] = 0;
        if (tid == 0) g_nvalid[b] = 0;
        return;
    }

    // --- level 1: histogram over key bits [52:64) ---
    for (int i = tid; i < NBINS; i += 1024) sm.u.hist[i] = 0;
    __syncthreads();
    for (int i = tid; i < cnt; i += 1024)
        atomicAdd(&sm.u.hist[(int)(g_ckey[b][i] >> 52)], 1);
    __syncthreads();
    scan_find_bin(sm, target, tid, lane, wid);
    __syncthreads();
    int T1 = sm.sT;
    int cntBefore = sm.sCum - sm.u.hist[T1];   // keys strictly below bin T1
    __syncthreads();                           // all reads done before reuse

    // --- level 2: histogram of bin-T1 keys over bits [40:52) ---
    for (int i = tid; i < NBINS; i += 1024) sm.u.hist[i] = 0;
    if (tid == 0) sm.sSel = 0;
    __syncthreads();
    for (int i = tid; i < cnt; i += 1024) {
        unsigned long long key = g_ckey[b][i];
        if ((int)(key >> 52) == T1)
            atomicAdd(&sm.u.hist[(int)(key >> 40) & 0xFFF], 1);
    }
    __syncthreads();
    scan_find_bin(sm, target - cntBefore, tid, lane, wid);
    __syncthreads();
    int T2 = sm.sT;
    int S = min(cntBefore + sm.sCum, SELC);    // S ~= target + few collisions

    // --- compact the selected superset ---
    for (int i = tid; i < cnt; i += 1024) {
        unsigned long long key = g_ckey[b][i];
        int b1 = (int)(key >> 52);
        if (b1 < T1 || (b1 == T1 && ((int)(key >> 40) & 0xFFF) <= T2)) {
            int pos = atomicAdd(&sm.sSel, 1);
            if (pos < SELC) sm.sel[pos] = key;
        }
    }
    __syncthreads();

    // --- bitonic sort of M = next_pow2(S) entries (512 or 1024) ---
    int M = 512;
    while (M < S) M <<= 1;
    for (int i = tid; i < M; i += 1024)
        if (i >= S) sm.sel[i] = ~0ULL;
    __syncthreads();
    for (int k = 2; k <= M; k <<= 1) {
        for (int j = k >> 1; j > 0; j >>= 1) {
            for (int t = tid; t < M; t += 1024) {
                int ixj = t ^ j;
                if (ixj > t) {
                    unsigned long long a = sm.sel[t], c2 = sm.sel[ixj];
                    bool up = ((t & k) == 0);
                    if ((a > c2) == up) { sm.sel[t] = c2; sm.sel[ixj] = a; }
                }
            }
            __syncthreads();
        }
    }

    int nv = target;
    if (tid == 0) g_nvalid[b] = nv;

    // --- decode junction tid (one thread per junction) ---
    float qx = 0.f, qy = 0.f;
    int myCell = -1;
    const float* rb = raw + (size_t)b * 9 * HWp;
    if (tid < Jp) {
        if (tid < nv) {
            unsigned long long key = sm.sel[tid];
            int p = (int)(key & 0xFFFFFFFFu);
            float offx = sigf(rb[7 * HWp + p]) - 0.5f;
            float offy = sigf(rb[8 * HWp + p]) - 0.5f;
            qx = (float)(p & 255) + offx + 0.5f;
            qy = (float)(p >> 8) + offy + 0.5f;
            myCell = (((int)qy >> 3) << 5) + ((int)qx >> 3);   // 32x32 cells of 8px
        }
        g_juncs[b][tid] = make_float2(qx, qy);
    }
    __syncthreads();          // done with sel/hist before reuse

    // --- build CSR cell grid ---
    sm.u.cnt1[tid] = 0;
    __syncthreads();
    if (myCell >= 0) atomicAdd(&sm.u.cnt1[myCell], 1);
    __syncthreads();
    int v = sm.u.cnt1[tid];
    int inc2 = v;
    #pragma unroll
    for (int d = 1; d < 32; d <<= 1) {
        int n = __shfl_up_sync(0xffffffffu, inc2, d);
        if (lane >= d) inc2 += n;
    }
    if (lane == 31) sm.warpsum[wid] = inc2;
    __syncthreads();
    if (wid == 0) {
        int vv = sm.warpsum[lane];
        int i2 = vv;
        #pragma unroll
        for (int d = 1; d < 32; d <<= 1) {
            int n = __shfl_up_sync(0xffffffffu, i2, d);
            if (lane >= d) i2 += n;
        }
        sm.warpsum[lane] = i2 - vv;
    }
    __syncthreads();
    int excl = sm.warpsum[wid] + inc2 - v;
    g_cellStart[b][tid] = excl;
    if (tid == 1023) g_cellStart[b][1024] = excl + v;   // == nv
    __syncthreads();
    sm.u.cnt1[tid] = excl;     // fill cursors
    __syncthreads();
    if (myCell >= 0) {
        int pos = atomicAdd(&sm.u.cnt1[myCell], 1);
        g_gpos[b][pos] = make_float2(qx, qy);
        g_gidx[b][pos] = tid;
    }
}

// ---------------------------------------------------------------------------
// Pruned nearest-junction search: any junction with d^2 < 10 lies within the
// cell window [e-sqrt(10), e+sqrt(10)]. (d, idx) lexicographic min reproduces
// the reference argmin first-index tie-break exactly.
// ---------------------------------------------------------------------------
__device__ __forceinline__ void nearest(int b, float ex, float ey,
                                        float& bd, int& bi) {
    int cx0 = ((int)fmaxf(ex - RADp, 0.0f)) >> 3;
    int cx1 = ((int)fminf(ex + RADp, 255.0f)) >> 3;
    int cy0 = ((int)fmaxf(ey - RADp, 0.0f)) >> 3;
    int cy1 = ((int)fminf(ey + RADp, 255.0f)) >> 3;
    for (int cy = cy0; cy <= cy1; cy++) {
        for (int cx = cx0; cx <= cx1; cx++) {
            int c = (cy << 5) + cx;
            int s = __ldg(&g_cellStart[b][c]);
            int e = __ldg(&g_cellStart[b][c + 1]);
            for (int k = s; k < e; k++) {
                float2 q = __ldg(&g_gpos[b][k]);
                int idx  = __ldg(&g_gidx[b][k]);
                float dx = ex - q.x, dy = ey - q.y;
                float d = fmaf(dy, dy, dx * dx);
                if (d < bd || (d == bd && idx < bi)) { bd = d; bi = idx; }
            }
        }
    }
}

// ---------------------------------------------------------------------------
// Per-pixel line decode + endpoint match + scatter (called twice per thread).
// ---------------------------------------------------------------------------
__device__ __forceinline__ void decode_match(int b, int p,
                                             const float* __restrict__ rb,
                                             float* __restrict__ counts,
                                             float* __restrict__ support) {
    float r0 = rb[p];
    float r1 = rb[HWp + p];
    float r2 = rb[2 * HWp + p];
    float r3 = rb[3 * HWp + p];

    float md0 = sigf(r0), md1 = sigf(r1), md2 = sigf(r2);
    float d   = sigf(r3);
    float theta = (md0 - 0.5f) * 6.28318530717958647692f;
    float cs = cosf(theta), ss = sinf(theta);
    float yst = tanf(md1 * 1.57079632679489661923f);
    float yed = tanf(-md2 * 1.57079632679489661923f);
    float ds = d * SCALEp;
    float x0 = (float)(p & 255);
    float y0 = (float)(p >> 8);
    float l0 = fminf(fmaxf((cs - ss * yst) * ds + x0, 0.0f), 255.0f);
    float l1 = fminf(fmaxf((ss + cs * yst) * ds + y0, 0.0f), 255.0f);
    float l2 = fminf(fmaxf((cs - ss * yed) * ds + x0, 0.0f), 255.0f);
    float l3 = fminf(fmaxf((ss + cs * yed) * ds + y0, 0.0f), 255.0f);

    float bd1 = 1e30f, bd2 = 1e30f;
    int   bi1 = Jp,    bi2 = Jp;
    nearest(b, l0, l1, bd1, bi1);
    nearest(b, l2, l3, bd2, bi2);

    if (bd1 < J2Lp && bd2 < J2Lp && bi1 != bi2) {
        int imin = min(bi1, bi2), imax = max(bi1, bi2);
        int g = b * JJp + imin * Jp + imax;
        atomicAdd(&counts[g], 1.0f);
        atomicAdd(&support[(size_t)g * 4 + 0], l0);
        atomicAdd(&support[(size_t)g * 4 + 1], l1);
        atomicAdd(&support[(size_t)g * 4 + 2], l2);
        atomicAdd(&support[(size_t)g * 4 + 3], l3);
    }
}

__global__ void __launch_bounds__(256) k_match(const float* __restrict__ raw,
                                               float* __restrict__ counts,
                                               float* __restrict__ support) {
    int b = blockIdx.y;
    const float* rb = raw + (size_t)b * 9 * HWp;
    int base = blockIdx.x * 512 + threadIdx.x;
    decode_match(b, base,       rb, counts, support);
    decode_match(b, base + 256, rb, counts, support);
}

// ---------------------------------------------------------------------------
// K4: lines_adj = (junc[i], junc[j]) masked by counts>0; writes every entry.
// Also resets candidate counters for the next graph replay.
// ---------------------------------------------------------------------------
__global__ void k_adj(const float* __restrict__ counts, float4* __restrict__ out) {
    int pid = blockIdx.x * blockDim.x + threadIdx.x;   // 0 .. Bp*JJp-1
    if (pid == 0) { g_ccnt[0] = 0; g_ccnt[1] = 0; }
    int b = pid >> 18;                                  // JJp = 2^18
    int q = pid & (JJp - 1);
    float c = counts[pid];
    float4 v = make_float4(0.f, 0.f, 0.f, 0.f);
    if (c > 0.0f) {
        float2 A  = g_juncs[b][q >> 9];
        float2 Bq = g_juncs[b][q & (Jp - 1)];
        v = make_float4(A.x, A.y, Bq.x, Bq.y);
    }
    out[pid] = v;
}

// ---------------------------------------------------------------------------
// Launch. Output layout: lines_adj [B*JJ*4] | counts [B*JJ] | support [B*JJ*4]
// ---------------------------------------------------------------------------
extern "C" void kernel_launch(void* const* d_in, const int* in_sizes, int n_in,
                              void* d_out, int out_size) {
    const float* raw = (const float*)d_in[0];
    float* out = (float*)d_out;
    float* counts  = out + (size_t)Bp * JJp * 4;
    float* support = counts + (size_t)Bp * JJp;

    dim3 gcand(256 + ZBLK, Bp);
    k_cand_zero<<<gcand, 256>>>(raw, (float4*)counts);
    k_topk<<<Bp, 1024>>>(raw);
    dim3 gmatch(HWp / 512, Bp);
    k_match<<<gmatch, 256>>>(raw, counts, support);
    k_adj<<<(Bp * JJp) / 256, 256>>>(counts, (float4*)out);
}

// round 6
// speedup vs baseline: 3.0413x; 1.1480x over previous
#include <cuda_runtime.h>
#include <stdint.h>

// Problem constants
#define HWp   65536      // 256*256
#define Bp    2
#define Jp    512
#define JJp   (Jp*Jp)    // 262144
#define CAPp  16384      // candidate capacity per batch (expected ~7.3k)
#define THp   0.008f
#define J2Lp  10.0f
#define SCALEp 5.0f
#define NBINS 4096       // histogram bins (12 bits per level)
#define SELC  1024       // compaction capacity (S ~= 515 after 2-level select)
#define RADp  3.16227766f // sqrt(10): max distance that can ever match
#define ZERO4 ((Bp*JJp*5)/4)  // float4 count of counts+support region
#define ZBLK  1280            // zeroing blocks per batch row (2*1280*256 == ZERO4)

// Scratch (static device globals — no allocation allowed)
__device__ unsigned long long  g_ckey[Bp][CAPp];
__device__ int                 g_ccnt[Bp];        // zero-init; reset by k_adj tail
__device__ int                 g_nvalid[Bp];
__device__ float2              g_juncs[Bp][Jp];
__device__ int                 g_cellStart[Bp][1025];  // CSR over 32x32 cells of 8px
__device__ float2              g_gpos[Bp][Jp];         // junction pos in cell order
__device__ int                 g_gidx[Bp][Jp];         // original top-k index

__device__ __forceinline__ float sigf(float x) { return 1.0f / (1.0f + expf(-x)); }

// ---------------------------------------------------------------------------
// K1: fused softmax-prob + 3x3 NMS + candidate append (smem halo tile),
// plus zeroing of the counts+support output region (extra blocks).
// prob = softmax(raw[:,5:7],axis=1)[:,1] computed with ONE expf:
// with m = max(r5,r6), one of exp(r5-m)/exp(r6-m) is exactly 1.0f, the other
// is expf(-|r6-r5|); select the matching quotient -> bit-identical result.
// key = (~float_bits(score) << 32) | pixel -> ascending == score desc,
// pixel-index asc on ties (matches jax.lax.top_k ordering).
// ---------------------------------------------------------------------------
__global__ void __launch_bounds__(256) k_cand_zero(const float* __restrict__ raw,
                                                   float4* __restrict__ zdst) {
    int b = blockIdx.y;
    if (blockIdx.x >= 256) {                       // zeroing blocks
        int zi = ((blockIdx.x - 256) + b * ZBLK) * 256 + threadIdx.x;
        if (zi < ZERO4) zdst[zi] = make_float4(0.f, 0.f, 0.f, 0.f);
        return;
    }
    __shared__ float sp[18 * 18];                  // 16x16 tile + 1px halo
    int tile = blockIdx.x;
    int tx0 = (tile & 15) << 4;
    int ty0 = (tile >> 4) << 4;
    const float* r5p = raw + (size_t)b * 9 * HWp + 5 * HWp;
    const float* r6p = raw + (size_t)b * 9 * HWp + 6 * HWp;

    for (int i = threadIdx.x; i < 324; i += 256) {
        int hx = tx0 - 1 + (i % 18);
        int hy = ty0 - 1 + (i / 18);
        float v = -1.0f;                           // OOB: below any prob (>0)
        if ((unsigned)hx < 256u && (unsigned)hy < 256u) {
            int p = (hy << 8) + hx;
            float r5 = r5p[p];
            float r6 = r6p[p];
            float e  = expf(-fabsf(r6 - r5));
            v = (r6 >= r5) ? 1.0f / (e + 1.0f) : e / (1.0f + e);
        }
        sp[i] = v;
    }
    __syncthreads();

    int lx = (threadIdx.x & 15) + 1;
    int ly = (threadIdx.x >> 4) + 1;
    float a = sp[ly * 18 + lx];
    if (a <= THp) return;
    int c = ly * 18 + lx;
    float mx;
    mx = fmaxf(sp[c - 19], sp[c - 18]);
    mx = fmaxf(mx, sp[c - 17]);
    mx = fmaxf(mx, sp[c - 1]);
    mx = fmaxf(mx, sp[c + 1]);
    mx = fmaxf(mx, sp[c + 17]);
    mx = fmaxf(mx, sp[c + 18]);
    mx = fmaxf(mx, sp[c + 19]);
    if (a >= mx) {                                 // a == maxpool(a) semantics
        int p = ((ty0 + ly - 1) << 8) + (tx0 + lx - 1);
        int pos = atomicAdd(&g_ccnt[b], 1);
        if (pos < CAPp) {
            unsigned inv = ~__float_as_uint(a);
            g_ckey[b][pos] = (((unsigned long long)inv) << 32) | (unsigned)p;
        }
    }
}

// ---------------------------------------------------------------------------
// K2: two-level radix select, barrier-lean bitonic sort (warp-shuffle
// sub-stages), junction decode, CSR spatial grid build. One block per batch.
// ---------------------------------------------------------------------------
struct SmemT {
    union {
        int hist[NBINS];                 // histogram (both levels) / scan
        int cnt1[1024];                  // cell counts, then fill cursors
    } u;
    unsigned long long sel[SELC];
    int warpsum[32];
    int sT, sCum, sSel;
};

// Find smallest bin T with cumulative >= target over sm.u.hist (4 bins/thread).
// Writes sm.sT (bin) and sm.sCum (inclusive cumulative through T).
// Caller must __syncthreads() before reading sm.sT / sm.sCum.
__device__ __forceinline__ void scan_find_bin(SmemT& sm, int target,
                                              int tid, int lane, int wid) {
    int base = tid * 4;
    int h0 = sm.u.hist[base], h1 = sm.u.hist[base+1];
    int h2 = sm.u.hist[base+2], h3 = sm.u.hist[base+3];
    int tot = h0 + h1 + h2 + h3;
    int inc = tot;
    #pragma unroll
    for (int d = 1; d < 32; d <<= 1) {
        int n = __shfl_up_sync(0xffffffffu, inc, d);
        if (lane >= d) inc += n;
    }
    if (lane == 31) sm.warpsum[wid] = inc;
    __syncthreads();
    if (wid == 0) {
        int v = sm.warpsum[lane];
        int i2 = v;
        #pragma unroll
        for (int d = 1; d < 32; d <<= 1) {
            int n = __shfl_up_sync(0xffffffffu, i2, d);
            if (lane >= d) i2 += n;
        }
        sm.warpsum[lane] = i2 - v;   // exclusive warp offsets
    }
    __syncthreads();
    int run = sm.warpsum[wid] + inc - tot;   // exclusive prefix for this thread
    int hh[4] = {h0, h1, h2, h3};
    #pragma unroll
    for (int i = 0; i < 4; i++) {
        run += hh[i];
        if (run >= target && run - hh[i] < target) { sm.sT = base + i; sm.sCum = run; }
    }
}

__device__ __forceinline__ unsigned long long bx(unsigned long long v, int j) {
    return __shfl_xor_sync(0xffffffffu, v, j);
}

__global__ void __launch_bounds__(1024) k_topk(const float* __restrict__ raw) {
    __shared__ SmemT sm;
    int b = blockIdx.x;
    int tid = threadIdx.x;
    int lane = tid & 31, wid = tid >> 5;
    int cnt = min(g_ccnt[b], CAPp);
    int target = min(Jp, cnt);

    if (cnt == 0) {   // defensive; never hit with this data
        if (tid < Jp) g_juncs[b][tid] = make_float2(0.f, 0.f);
        g_cellStart[b][tid] = 0;
        if (tid == 0) { g_cellStart[b][1024] = 0; g_nvalid[b] = 0; }
        return;
    }

    // --- level 1: histogram over key bits [52:64) ---
    for (int i = tid; i < NBINS; i += 1024) sm.u.hist[i] = 0;
    __syncthreads();
    for (int i = tid; i < cnt; i += 1024)
        atomicAdd(&sm.u.hist[(int)(g_ckey[b][i] >> 52)], 1);
    __syncthreads();
    scan_find_bin(sm, target, tid, lane, wid);
    __syncthreads();
    int T1 = sm.sT;
    int cntBefore = sm.sCum - sm.u.hist[T1];   // keys strictly below bin T1
    __syncthreads();                           // all reads done before reuse

    // --- level 2: histogram of bin-T1 keys over bits [40:52) ---
    for (int i = tid; i < NBINS; i += 1024) sm.u.hist[i] = 0;
    if (tid == 0) sm.sSel = 0;
    __syncthreads();
    for (int i = tid; i < cnt; i += 1024) {
        unsigned long long key = g_ckey[b][i];
        if ((int)(key >> 52) == T1)
            atomicAdd(&sm.u.hist[(int)(key >> 40) & 0xFFF], 1);
    }
    __syncthreads();
    scan_find_bin(sm, target - cntBefore, tid, lane, wid);
    __syncthreads();
    int T2 = sm.sT;
    int S = min(cntBefore + sm.sCum, SELC);    // S ~= target + few collisions

    // --- compact the selected superset ---
    for (int i = tid; i < cnt; i += 1024) {
        unsigned long long key = g_ckey[b][i];
        int b1 = (int)(key >> 52);
        if (b1 < T1 || (b1 == T1 && ((int)(key >> 40) & 0xFFF) <= T2)) {
            int pos = atomicAdd(&sm.sSel, 1);
            if (pos < SELC) sm.sel[pos] = key;
        }
    }
    __syncthreads();
    if (tid >= S) sm.sel[tid] = ~0ULL;        // pad to M=1024
    __syncthreads();

    // --- bitonic sort of M=1024, barrier-lean:
    //     stages k=2..32 fully in registers (intra-warp shuffles);
    //     stages k>=64: smem passes for j>=32, 5-shuffle register tail.
    //     Same comparison network as a plain bitonic sort -> identical order.
    {
        unsigned long long e = sm.sel[tid];
        #pragma unroll
        for (int k = 2; k <= 32; k <<= 1) {
            #pragma unroll
            for (int j = k >> 1; j > 0; j >>= 1) {
                unsigned long long o = bx(e, j);
                bool takeMin = ((tid & k) == 0) == ((tid & j) == 0);
                e = ((e < o) == takeMin) ? e : o;
            }
        }
        sm.sel[tid] = e;
        __syncthreads();
        for (int k = 64; k <= 1024; k <<= 1) {
            for (int j = k >> 1; j >= 32; j >>= 1) {
                int ixj = tid ^ j;
                if (ixj > tid) {
                    unsigned long long a = sm.sel[tid], c2 = sm.sel[ixj];
                    bool up = ((tid & k) == 0);
                    if ((a > c2) == up) { sm.sel[tid] = c2; sm.sel[ixj] = a; }
                }
                __syncthreads();
            }
            e = sm.sel[tid];
            #pragma unroll
            for (int j = 16; j > 0; j >>= 1) {
                unsigned long long o = bx(e, j);
                bool takeMin = ((tid & k) == 0) == ((tid & j) == 0);
                e = ((e < o) == takeMin) ? e : o;
            }
            sm.sel[tid] = e;
            __syncthreads();
        }
    }

    int nv = target;
    if (tid == 0) g_nvalid[b] = nv;

    // --- decode junction tid (one thread per junction) ---
    float qx = 0.f, qy = 0.f;
    int myCell = -1;
    const float* rb = raw + (size_t)b * 9 * HWp;
    if (tid < Jp) {
        if (tid < nv) {
            unsigned long long key = sm.sel[tid];
            int p = (int)(key & 0xFFFFFFFFu);
            float offx = sigf(rb[7 * HWp + p]) - 0.5f;
            float offy = sigf(rb[8 * HWp + p]) - 0.5f;
            qx = (float)(p & 255) + offx + 0.5f;
            qy = (float)(p >> 8) + offy + 0.5f;
            myCell = (((int)qy >> 3) << 5) + ((int)qx >> 3);   // 32x32 cells of 8px
        }
        g_juncs[b][tid] = make_float2(qx, qy);
    }
    __syncthreads();          // done with sel/hist before reuse

    // --- build CSR cell grid ---
    sm.u.cnt1[tid] = 0;
    __syncthreads();
    if (myCell >= 0) atomicAdd(&sm.u.cnt1[myCell], 1);
    __syncthreads();
    int v = sm.u.cnt1[tid];
    int inc2 = v;
    #pragma unroll
    for (int d = 1; d < 32; d <<= 1) {
        int n = __shfl_up_sync(0xffffffffu, inc2, d);
        if (lane >= d) inc2 += n;
    }
    if (lane == 31) sm.warpsum[wid] = inc2;
    __syncthreads();
    if (wid == 0) {
        int vv = sm.warpsum[lane];
        int i2 = vv;
        #pragma unroll
        for (int d = 1; d < 32; d <<= 1) {
            int n = __shfl_up_sync(0xffffffffu, i2, d);
            if (lane >= d) i2 += n;
        }
        sm.warpsum[lane] = i2 - vv;
    }
    __syncthreads();
    int excl = sm.warpsum[wid] + inc2 - v;
    g_cellStart[b][tid] = excl;
    if (tid == 1023) g_cellStart[b][1024] = excl + v;   // == nv
    __syncthreads();
    sm.u.cnt1[tid] = excl;     // fill cursors
    __syncthreads();
    if (myCell >= 0) {
        int pos = atomicAdd(&sm.u.cnt1[myCell], 1);
        g_gpos[b][pos] = make_float2(qx, qy);
        g_gidx[b][pos] = tid;
    }
}

// ---------------------------------------------------------------------------
// Pruned nearest-junction search: any junction with d^2 < 10 lies within the
// cell window [e-sqrt(10), e+sqrt(10)]. (d, idx) lexicographic min reproduces
// the reference argmin first-index tie-break exactly.
// ---------------------------------------------------------------------------
__device__ __forceinline__ void nearest(int b, float ex, float ey,
                                        float& bd, int& bi) {
    int cx0 = ((int)fmaxf(ex - RADp, 0.0f)) >> 3;
    int cx1 = ((int)fminf(ex + RADp, 255.0f)) >> 3;
    int cy0 = ((int)fmaxf(ey - RADp, 0.0f)) >> 3;
    int cy1 = ((int)fminf(ey + RADp, 255.0f)) >> 3;
    for (int cy = cy0; cy <= cy1; cy++) {
        for (int cx = cx0; cx <= cx1; cx++) {
            int c = (cy << 5) + cx;
            int s = __ldg(&g_cellStart[b][c]);
            int e = __ldg(&g_cellStart[b][c + 1]);
            for (int k = s; k < e; k++) {
                float2 q = __ldg(&g_gpos[b][k]);
                int idx  = __ldg(&g_gidx[b][k]);
                float dx = ex - q.x, dy = ey - q.y;
                float d = fmaf(dy, dy, dx * dx);
                if (d < bd || (d == bd && idx < bi)) { bd = d; bi = idx; }
            }
        }
    }
}

// ---------------------------------------------------------------------------
// Per-pixel line decode + endpoint match + scatter (called twice per thread).
// ---------------------------------------------------------------------------
__device__ __forceinline__ void decode_match(int b, int p,
                                             const float* __restrict__ rb,
                                             float* __restrict__ counts,
                                             float* __restrict__ support) {
    float r0 = rb[p];
    float r1 = rb[HWp + p];
    float r2 = rb[2 * HWp + p];
    float r3 = rb[3 * HWp + p];

    float md0 = sigf(r0), md1 = sigf(r1), md2 = sigf(r2);
    float d   = sigf(r3);
    float theta = (md0 - 0.5f) * 6.28318530717958647692f;
    float cs = cosf(theta), ss = sinf(theta);
    float yst = tanf(md1 * 1.57079632679489661923f);
    float yed = tanf(-md2 * 1.57079632679489661923f);
    float ds = d * SCALEp;
    float x0 = (float)(p & 255);
    float y0 = (float)(p >> 8);
    float l0 = fminf(fmaxf((cs - ss * yst) * ds + x0, 0.0f), 255.0f);
    float l1 = fminf(fmaxf((ss + cs * yst) * ds + y0, 0.0f), 255.0f);
    float l2 = fminf(fmaxf((cs - ss * yed) * ds + x0, 0.0f), 255.0f);
    float l3 = fminf(fmaxf((ss + cs * yed) * ds + y0, 0.0f), 255.0f);

    float bd1 = 1e30f, bd2 = 1e30f;
    int   bi1 = Jp,    bi2 = Jp;
    nearest(b, l0, l1, bd1, bi1);
    nearest(b, l2, l3, bd2, bi2);

    if (bd1 < J2Lp && bd2 < J2Lp && bi1 != bi2) {
        int imin = min(bi1, bi2), imax = max(bi1, bi2);
        int g = b * JJp + imin * Jp + imax;
        atomicAdd(&counts[g], 1.0f);
        atomicAdd(&support[(size_t)g * 4 + 0], l0);
        atomicAdd(&support[(size_t)g * 4 + 1], l1);
        atomicAdd(&support[(size_t)g * 4 + 2], l2);
        atomicAdd(&support[(size_t)g * 4 + 3], l3);
    }
}

__global__ void __launch_bounds__(256) k_match(const float* __restrict__ raw,
                                               float* __restrict__ counts,
                                               float* __restrict__ support) {
    int b = blockIdx.y;
    const float* rb = raw + (size_t)b * 9 * HWp;
    int base = blockIdx.x * 512 + threadIdx.x;
    decode_match(b, base,       rb, counts, support);
    decode_match(b, base + 256, rb, counts, support);
}

// ---------------------------------------------------------------------------
// K4: lines_adj = (junc[i], junc[j]) masked by counts>0. 4 pair-ids/thread:
// one float4 counts load, shared junc[i] (identical across the 4), 64B store.
// Also resets candidate counters for the next graph replay.
// ---------------------------------------------------------------------------
__global__ void k_adj(const float4* __restrict__ counts4, float4* __restrict__ out) {
    int t = blockIdx.x * blockDim.x + threadIdx.x;   // 0 .. Bp*JJp/4-1
    if (t == 0) { g_ccnt[0] = 0; g_ccnt[1] = 0; }
    int q4 = t << 2;
    int b = q4 >> 18;                                 // JJp = 2^18
    int q = q4 & (JJp - 1);
    float4 c = counts4[t];
    float4 v0 = make_float4(0.f,0.f,0.f,0.f), v1 = v0, v2 = v0, v3 = v0;
    if (c.x > 0.f || c.y > 0.f || c.z > 0.f || c.w > 0.f) {
        float2 A = g_juncs[b][q >> 9];                // same i for all 4 lanes
        int j0 = q & (Jp - 1);
        if (c.x > 0.f) { float2 Bq = g_juncs[b][j0    ]; v0 = make_float4(A.x, A.y, Bq.x, Bq.y); }
        if (c.y > 0.f) { float2 Bq = g_juncs[b][j0 + 1]; v1 = make_float4(A.x, A.y, Bq.x, Bq.y); }
        if (c.z > 0.f) { float2 Bq = g_juncs[b][j0 + 2]; v2 = make_float4(A.x, A.y, Bq.x, Bq.y); }
        if (c.w > 0.f) { float2 Bq = g_juncs[b][j0 + 3]; v3 = make_float4(A.x, A.y, Bq.x, Bq.y); }
    }
    float4* o = out + (size_t)q4;
    o[0] = v0; o[1] = v1; o[2] = v2; o[3] = v3;
}

// ---------------------------------------------------------------------------
// Launch. Output layout: lines_adj [B*JJ*4] | counts [B*JJ] | support [B*JJ*4]
// ---------------------------------------------------------------------------
extern "C" void kernel_launch(void* const* d_in, const int* in_sizes, int n_in,
                              void* d_out, int out_size) {
    const float* raw = (const float*)d_in[0];
    float* out = (float*)d_out;
    float* counts  = out + (size_t)Bp * JJp * 4;
    float* support = counts + (size_t)Bp * JJp;

    dim3 gcand(256 + ZBLK, Bp);
    k_cand_zero<<<gcand, 256>>>(raw, (float4*)counts);
    k_topk<<<Bp, 1024>>>(raw);
    dim3 gmatch(HWp / 512, Bp);
    k_match<<<gmatch, 256>>>(raw, counts, support);
    k_adj<<<(Bp * JJp / 4) / 256, 256>>>((const float4*)counts, (float4*)out);
}

// round 7
// speedup vs baseline: 3.1960x; 1.0509x over previous
#include <cuda_runtime.h>
#include <stdint.h>

// Problem constants
#define HWp   65536      // 256*256
#define Bp    2
#define Jp    512
#define JJp   (Jp*Jp)    // 262144
#define CAPp  16384      // candidate capacity per batch (expected ~7.3k)
#define THp   0.008f
#define J2Lp  10.0f
#define SCALEp 5.0f
#define NBINS 4096       // histogram bins (12 bits per level)
#define SELC  1024       // compaction capacity (S ~= 515 after 2-level select)
#define RADp  3.16227766f // sqrt(10): max distance that can ever match
#define ZERO4 ((Bp*JJp*9)/4)  // float4 count of the ENTIRE output region
#define ZBLK  1152            // zero blocks per batch row; each covers 512 float4
                              // (2*1152*512 == ZERO4)

// Scratch (static device globals — no allocation allowed)
__device__ unsigned long long  g_ckey[Bp][CAPp];
__device__ int                 g_ccnt[Bp];        // zero-init; reset by k_match
__device__ int                 g_nvalid[Bp];
__device__ float2              g_juncs[Bp][Jp];
__device__ int                 g_cellStart[Bp][1025];  // CSR over 32x32 cells of 8px
__device__ float2              g_gpos[Bp][Jp];         // junction pos in cell order
__device__ int                 g_gidx[Bp][Jp];         // original top-k index

__device__ __forceinline__ float sigf(float x) { return 1.0f / (1.0f + expf(-x)); }

// ---------------------------------------------------------------------------
// K1: fused softmax-prob + 3x3 NMS + candidate append (smem halo tile),
// plus zeroing of the FULL output region (extra blocks, run concurrently).
// prob = softmax(raw[:,5:7],axis=1)[:,1] with ONE expf: one of the two
// exponentials is exactly 1.0f after max-subtraction -> select the quotient;
// bit-identical to the two-expf form.
// key = (~float_bits(score) << 32) | pixel -> ascending == score desc,
// pixel-index asc on ties (matches jax.lax.top_k ordering).
// ---------------------------------------------------------------------------
__global__ void __launch_bounds__(256) k_cand_zero(const float* __restrict__ raw,
                                                   float4* __restrict__ zdst) {
    int b = blockIdx.y;
    if (blockIdx.x >= 256) {                       // zeroing blocks
        int zi = ((blockIdx.x - 256) + b * ZBLK) * 512 + threadIdx.x;
        float4 z = make_float4(0.f, 0.f, 0.f, 0.f);
        if (zi < ZERO4) zdst[zi] = z;
        if (zi + 256 < ZERO4) zdst[zi + 256] = z;
        return;
    }
    __shared__ float sp[18 * 18];                  // 16x16 tile + 1px halo
    int tile = blockIdx.x;
    int tx0 = (tile & 15) << 4;
    int ty0 = (tile >> 4) << 4;
    const float* r5p = raw + (size_t)b * 9 * HWp + 5 * HWp;
    const float* r6p = raw + (size_t)b * 9 * HWp + 6 * HWp;

    for (int i = threadIdx.x; i < 324; i += 256) {
        int hx = tx0 - 1 + (i % 18);
        int hy = ty0 - 1 + (i / 18);
        float v = -1.0f;                           // OOB: below any prob (>0)
        if ((unsigned)hx < 256u && (unsigned)hy < 256u) {
            int p = (hy << 8) + hx;
            float r5 = r5p[p];
            float r6 = r6p[p];
            float e  = expf(-fabsf(r6 - r5));
            v = (r6 >= r5) ? 1.0f / (e + 1.0f) : e / (1.0f + e);
        }
        sp[i] = v;
    }
    __syncthreads();

    int lx = (threadIdx.x & 15) + 1;
    int ly = (threadIdx.x >> 4) + 1;
    float a = sp[ly * 18 + lx];
    if (a <= THp) return;
    int c = ly * 18 + lx;
    float mx;
    mx = fmaxf(sp[c - 19], sp[c - 18]);
    mx = fmaxf(mx, sp[c - 17]);
    mx = fmaxf(mx, sp[c - 1]);
    mx = fmaxf(mx, sp[c + 1]);
    mx = fmaxf(mx, sp[c + 17]);
    mx = fmaxf(mx, sp[c + 18]);
    mx = fmaxf(mx, sp[c + 19]);
    if (a >= mx) {                                 // a == maxpool(a) semantics
        int p = ((ty0 + ly - 1) << 8) + (tx0 + lx - 1);
        int pos = atomicAdd(&g_ccnt[b], 1);
        if (pos < CAPp) {
            unsigned inv = ~__float_as_uint(a);
            g_ckey[b][pos] = (((unsigned long long)inv) << 32) | (unsigned)p;
        }
    }
}

// ---------------------------------------------------------------------------
// K2: two-level radix select, barrier-lean bitonic sort (warp-shuffle
// sub-stages), junction decode, CSR spatial grid build. One block per batch.
// ---------------------------------------------------------------------------
struct SmemT {
    union {
        int hist[NBINS];                 // histogram (both levels) / scan
        int cnt1[1024];                  // cell counts, then fill cursors
    } u;
    unsigned long long sel[SELC];
    int warpsum[32];
    int sT, sCum, sSel;
};

// Find smallest bin T with cumulative >= target over sm.u.hist (4 bins/thread).
// Writes sm.sT (bin) and sm.sCum (inclusive cumulative through T).
// Caller must __syncthreads() before reading sm.sT / sm.sCum.
__device__ __forceinline__ void scan_find_bin(SmemT& sm, int target,
                                              int tid, int lane, int wid) {
    int base = tid * 4;
    int h0 = sm.u.hist[base], h1 = sm.u.hist[base+1];
    int h2 = sm.u.hist[base+2], h3 = sm.u.hist[base+3];
    int tot = h0 + h1 + h2 + h3;
    int inc = tot;
    #pragma unroll
    for (int d = 1; d < 32; d <<= 1) {
        int n = __shfl_up_sync(0xffffffffu, inc, d);
        if (lane >= d) inc += n;
    }
    if (lane == 31) sm.warpsum[wid] = inc;
    __syncthreads();
    if (wid == 0) {
        int v = sm.warpsum[lane];
        int i2 = v;
        #pragma unroll
        for (int d = 1; d < 32; d <<= 1) {
            int n = __shfl_up_sync(0xffffffffu, i2, d);
            if (lane >= d) i2 += n;
        }
        sm.warpsum[lane] = i2 - v;   // exclusive warp offsets
    }
    __syncthreads();
    int run = sm.warpsum[wid] + inc - tot;   // exclusive prefix for this thread
    int hh[4] = {h0, h1, h2, h3};
    #pragma unroll
    for (int i = 0; i < 4; i++) {
        run += hh[i];
        if (run >= target && run - hh[i] < target) { sm.sT = base + i; sm.sCum = run; }
    }
}

__device__ __forceinline__ unsigned long long bx(unsigned long long v, int j) {
    return __shfl_xor_sync(0xffffffffu, v, j);
}

__global__ void __launch_bounds__(1024) k_topk(const float* __restrict__ raw) {
    __shared__ SmemT sm;
    int b = blockIdx.x;
    int tid = threadIdx.x;
    int lane = tid & 31, wid = tid >> 5;
    int cnt = min(g_ccnt[b], CAPp);
    int target = min(Jp, cnt);

    if (cnt == 0) {   // defensive; never hit with this data
        if (tid < Jp) g_juncs[b][tid] = make_float2(0.f, 0.f);
        g_cellStart[b][tid] = 0;
        if (tid == 0) { g_cellStart[b][1024] = 0; g_nvalid[b] = 0; }
        return;
    }

    // --- level 1: histogram over key bits [52:64) ---
    for (int i = tid; i < NBINS; i += 1024) sm.u.hist[i] = 0;
    __syncthreads();
    for (int i = tid; i < cnt; i += 1024)
        atomicAdd(&sm.u.hist[(int)(g_ckey[b][i] >> 52)], 1);
    __syncthreads();
    scan_find_bin(sm, target, tid, lane, wid);
    __syncthreads();
    int T1 = sm.sT;
    int cntBefore = sm.sCum - sm.u.hist[T1];   // keys strictly below bin T1
    __syncthreads();                           // all reads done before reuse

    // --- level 2: histogram of bin-T1 keys over bits [40:52) ---
    for (int i = tid; i < NBINS; i += 1024) sm.u.hist[i] = 0;
    if (tid == 0) sm.sSel = 0;
    __syncthreads();
    for (int i = tid; i < cnt; i += 1024) {
        unsigned long long key = g_ckey[b][i];
        if ((int)(key >> 52) == T1)
            atomicAdd(&sm.u.hist[(int)(key >> 40) & 0xFFF], 1);
    }
    __syncthreads();
    scan_find_bin(sm, target - cntBefore, tid, lane, wid);
    __syncthreads();
    int T2 = sm.sT;
    int S = min(cntBefore + sm.sCum, SELC);    // S ~= target + few collisions

    // --- compact the selected superset ---
    for (int i = tid; i < cnt; i += 1024) {
        unsigned long long key = g_ckey[b][i];
        int b1 = (int)(key >> 52);
        if (b1 < T1 || (b1 == T1 && ((int)(key >> 40) & 0xFFF) <= T2)) {
            int pos = atomicAdd(&sm.sSel, 1);
            if (pos < SELC) sm.sel[pos] = key;
        }
    }
    __syncthreads();
    if (tid >= S) sm.sel[tid] = ~0ULL;        // pad to M=1024
    __syncthreads();

    // --- bitonic sort of M=1024, barrier-lean:
    //     stages k=2..32 fully in registers (intra-warp shuffles);
    //     stages k>=64: smem passes for j>=32, 5-shuffle register tail.
    //     Same comparison network as a plain bitonic sort -> identical order.
    {
        unsigned long long e = sm.sel[tid];
        #pragma unroll
        for (int k = 2; k <= 32; k <<= 1) {
            #pragma unroll
            for (int j = k >> 1; j > 0; j >>= 1) {
                unsigned long long o = bx(e, j);
                bool takeMin = ((tid & k) == 0) == ((tid & j) == 0);
                e = ((e < o) == takeMin) ? e : o;
            }
        }
        sm.sel[tid] = e;
        __syncthreads();
        for (int k = 64; k <= 1024; k <<= 1) {
            for (int j = k >> 1; j >= 32; j >>= 1) {
                int ixj = tid ^ j;
                if (ixj > tid) {
                    unsigned long long a = sm.sel[tid], c2 = sm.sel[ixj];
                    bool up = ((tid & k) == 0);
                    if ((a > c2) == up) { sm.sel[tid] = c2; sm.sel[ixj] = a; }
                }
                __syncthreads();
            }
            e = sm.sel[tid];
            #pragma unroll
            for (int j = 16; j > 0; j >>= 1) {
                unsigned long long o = bx(e, j);
                bool takeMin = ((tid & k) == 0) == ((tid & j) == 0);
                e = ((e < o) == takeMin) ? e : o;
            }
            sm.sel[tid] = e;
            __syncthreads();
        }
    }

    int nv = target;
    if (tid == 0) g_nvalid[b] = nv;

    // --- decode junction tid (one thread per junction) ---
    float qx = 0.f, qy = 0.f;
    int myCell = -1;
    const float* rb = raw + (size_t)b * 9 * HWp;
    if (tid < Jp) {
        if (tid < nv) {
            unsigned long long key = sm.sel[tid];
            int p = (int)(key & 0xFFFFFFFFu);
            float offx = sigf(rb[7 * HWp + p]) - 0.5f;
            float offy = sigf(rb[8 * HWp + p]) - 0.5f;
            qx = (float)(p & 255) + offx + 0.5f;
            qy = (float)(p >> 8) + offy + 0.5f;
            myCell = (((int)qy >> 3) << 5) + ((int)qx >> 3);   // 32x32 cells of 8px
        }
        g_juncs[b][tid] = make_float2(qx, qy);
    }
    __syncthreads();          // done with sel/hist before reuse

    // --- build CSR cell grid ---
    sm.u.cnt1[tid] = 0;
    __syncthreads();
    if (myCell >= 0) atomicAdd(&sm.u.cnt1[myCell], 1);
    __syncthreads();
    int v = sm.u.cnt1[tid];
    int inc2 = v;
    #pragma unroll
    for (int d = 1; d < 32; d <<= 1) {
        int n = __shfl_up_sync(0xffffffffu, inc2, d);
        if (lane >= d) inc2 += n;
    }
    if (lane == 31) sm.warpsum[wid] = inc2;
    __syncthreads();
    if (wid == 0) {
        int vv = sm.warpsum[lane];
        int i2 = vv;
        #pragma unroll
        for (int d = 1; d < 32; d <<= 1) {
            int n = __shfl_up_sync(0xffffffffu, i2, d);
            if (lane >= d) i2 += n;
        }
        sm.warpsum[lane] = i2 - vv;
    }
    __syncthreads();
    int excl = sm.warpsum[wid] + inc2 - v;
    g_cellStart[b][tid] = excl;
    if (tid == 1023) g_cellStart[b][1024] = excl + v;   // == nv
    __syncthreads();
    sm.u.cnt1[tid] = excl;     // fill cursors
    __syncthreads();
    if (myCell >= 0) {
        int pos = atomicAdd(&sm.u.cnt1[myCell], 1);
        g_gpos[b][pos] = make_float2(qx, qy);
        g_gidx[b][pos] = tid;
    }
}

// ---------------------------------------------------------------------------
// Pruned nearest-junction search: any junction with d^2 < 10 lies within the
// cell window [e-sqrt(10), e+sqrt(10)]. (d, idx) lexicographic min reproduces
// the reference argmin first-index tie-break exactly.
// ---------------------------------------------------------------------------
__device__ __forceinline__ void nearest(int b, float ex, float ey,
                                        float& bd, int& bi) {
    int cx0 = ((int)fmaxf(ex - RADp, 0.0f)) >> 3;
    int cx1 = ((int)fminf(ex + RADp, 255.0f)) >> 3;
    int cy0 = ((int)fmaxf(ey - RADp, 0.0f)) >> 3;
    int cy1 = ((int)fminf(ey + RADp, 255.0f)) >> 3;
    for (int cy = cy0; cy <= cy1; cy++) {
        for (int cx = cx0; cx <= cx1; cx++) {
            int c = (cy << 5) + cx;
            int s = __ldg(&g_cellStart[b][c]);
            int e = __ldg(&g_cellStart[b][c + 1]);
            for (int k = s; k < e; k++) {
                float2 q = __ldg(&g_gpos[b][k]);
                int idx  = __ldg(&g_gidx[b][k]);
                float dx = ex - q.x, dy = ey - q.y;
                float d = fmaf(dy, dy, dx * dx);
                if (d < bd || (d == bd && idx < bi)) { bd = d; bi = idx; }
            }
        }
    }
}

// ---------------------------------------------------------------------------
// Per-pixel line decode + endpoint match + scatter. The FIRST thread to touch
// a bucket (atomicAdd returns 0) also writes lines_adj[g] — the value depends
// only on g, so the winner's identity is irrelevant (deterministic output).
// ---------------------------------------------------------------------------
__device__ __forceinline__ void decode_match(int b, int p,
                                             const float* __restrict__ rb,
                                             float4* __restrict__ lines,
                                             float* __restrict__ counts,
                                             float* __restrict__ support) {
    float r0 = rb[p];
    float r1 = rb[HWp + p];
    float r2 = rb[2 * HWp + p];
    float r3 = rb[3 * HWp + p];

    float md0 = sigf(r0), md1 = sigf(r1), md2 = sigf(r2);
    float d   = sigf(r3);
    float theta = (md0 - 0.5f) * 6.28318530717958647692f;
    float cs, ss;
    sincosf(theta, &ss, &cs);
    float yst = tanf(md1 * 1.57079632679489661923f);
    float yed = tanf(-md2 * 1.57079632679489661923f);
    float ds = d * SCALEp;
    float x0 = (float)(p & 255);
    float y0 = (float)(p >> 8);
    float l0 = fminf(fmaxf((cs - ss * yst) * ds + x0, 0.0f), 255.0f);
    float l1 = fminf(fmaxf((ss + cs * yst) * ds + y0, 0.0f), 255.0f);
    float l2 = fminf(fmaxf((cs - ss * yed) * ds + x0, 0.0f), 255.0f);
    float l3 = fminf(fmaxf((ss + cs * yed) * ds + y0, 0.0f), 255.0f);

    float bd1 = 1e30f, bd2 = 1e30f;
    int   bi1 = Jp,    bi2 = Jp;
    nearest(b, l0, l1, bd1, bi1);
    nearest(b, l2, l3, bd2, bi2);

    if (bd1 < J2Lp && bd2 < J2Lp && bi1 != bi2) {
        int imin = min(bi1, bi2), imax = max(bi1, bi2);
        int g = b * JJp + imin * Jp + imax;
        float old = atomicAdd(&counts[g], 1.0f);
        atomicAdd(&support[(size_t)g * 4 + 0], l0);
        atomicAdd(&support[(size_t)g * 4 + 1], l1);
        atomicAdd(&support[(size_t)g * 4 + 2], l2);
        atomicAdd(&support[(size_t)g * 4 + 3], l3);
        if (old == 0.0f) {
            float2 A  = g_juncs[b][imin];
            float2 Bq = g_juncs[b][imax];
            lines[g] = make_float4(A.x, A.y, Bq.x, Bq.y);
        }
    }
}

__global__ void __launch_bounds__(256) k_match(const float* __restrict__ raw,
                                               float4* __restrict__ lines,
                                               float* __restrict__ counts,
                                               float* __restrict__ support) {
    int b = blockIdx.y;
    if (b == 0 && blockIdx.x == 0 && threadIdx.x == 0) {
        g_ccnt[0] = 0; g_ccnt[1] = 0;    // reset for next replay (topk already consumed)
    }
    const float* rb = raw + (size_t)b * 9 * HWp;
    int base = blockIdx.x * 512 + threadIdx.x;
    decode_match(b, base,       rb, lines, counts, support);
    decode_match(b, base + 256, rb, lines, counts, support);
}

// ---------------------------------------------------------------------------
// Launch. Output layout: lines_adj [B*JJ*4] | counts [B*JJ] | support [B*JJ*4]
// ---------------------------------------------------------------------------
extern "C" void kernel_launch(void* const* d_in, const int* in_sizes, int n_in,
                              void* d_out, int out_size) {
    const float* raw = (const float*)d_in[0];
    float* out = (float*)d_out;
    float* counts  = out + (size_t)Bp * JJp * 4;
    float* support = counts + (size_t)Bp * JJp;

    dim3 gcand(256 + ZBLK, Bp);
    k_cand_zero<<<gcand, 256>>>(raw, (float4*)out);   // zeroes the WHOLE output
    k_topk<<<Bp, 1024>>>(raw);
    dim3 gmatch(HWp / 512, Bp);
    k_match<<<gmatch, 256>>>(raw, (float4*)out, counts, support);
}

// round 8
// speedup vs baseline: 3.2700x; 1.0231x over previous
#include <cuda_runtime.h>
#include <stdint.h>

// Problem constants
#define HWp   65536      // 256*256
#define Bp    2
#define Jp    512
#define JJp   (Jp*Jp)    // 262144
#define CAPp  16384      // candidate capacity per batch (expected ~7.3k)
#define THp   0.008f
#define J2Lp  10.0f
#define SCALEp 5.0f
#define NBINS 4096       // histogram bins (12 bits per level)
#define SELC  1024       // compaction capacity (S ~= 515 after 2-level select)
#define RADp  3.16227766f // sqrt(10): max distance that can ever match
#define ZERO4 ((Bp*JJp*9)/4)  // float4 count of the ENTIRE output region = 1179648
#define ZBLKC 384             // zero blocks per batch in k_cand (512 float4 each)
#define ZC4   (Bp*ZBLKC*512)  // float4s zeroed by k_cand = 393216
#define ZBLKT 192             // zero blocks in k_topk (4096 float4 each) = 786432

// Scratch (static device globals — no allocation allowed)
__device__ unsigned long long  g_ckey[Bp][CAPp];
__device__ int                 g_ccnt[Bp];        // zero-init; reset by k_match
__device__ int                 g_nvalid[Bp];
__device__ float2              g_juncs[Bp][Jp];
__device__ int                 g_cellStart[Bp][1025];  // CSR over 32x32 cells of 8px
__device__ float2              g_gpos[Bp][Jp];         // junction pos in cell order
__device__ int                 g_gidx[Bp][Jp];         // original top-k index

__device__ __forceinline__ float sigf(float x) { return 1.0f / (1.0f + expf(-x)); }

// ---------------------------------------------------------------------------
// K1: fused softmax-prob + 3x3 NMS + candidate append (smem halo tile),
// plus 1/3 of the output-zeroing (extra blocks; the rest rides on k_topk's
// idle SMs). prob = softmax(raw[:,5:7],axis=1)[:,1] with ONE expf (one of the
// two exponentials is exactly 1.0f after max-subtraction) -> bit-identical.
// key = (~float_bits(score) << 32) | pixel -> ascending == score desc,
// pixel-index asc on ties (matches jax.lax.top_k ordering).
// ---------------------------------------------------------------------------
__global__ void __launch_bounds__(256) k_cand_zero(const float* __restrict__ raw,
                                                   float4* __restrict__ zdst) {
    int b = blockIdx.y;
    if (blockIdx.x >= 256) {                       // zeroing blocks: [0, ZC4)
        int zi = ((blockIdx.x - 256) + b * ZBLKC) * 512 + threadIdx.x;
        float4 z = make_float4(0.f, 0.f, 0.f, 0.f);
        zdst[zi] = z;
        zdst[zi + 256] = z;
        return;
    }
    __shared__ float sp[18 * 18];                  // 16x16 tile + 1px halo
    int tile = blockIdx.x;
    int tx0 = (tile & 15) << 4;
    int ty0 = (tile >> 4) << 4;
    const float* r5p = raw + (size_t)b * 9 * HWp + 5 * HWp;
    const float* r6p = raw + (size_t)b * 9 * HWp + 6 * HWp;

    #pragma unroll 2
    for (int i = threadIdx.x; i < 324; i += 256) {
        int hx = tx0 - 1 + (i % 18);
        int hy = ty0 - 1 + (i / 18);
        float v = -1.0f;                           // OOB: below any prob (>0)
        if ((unsigned)hx < 256u && (unsigned)hy < 256u) {
            int p = (hy << 8) + hx;
            float r5 = r5p[p];
            float r6 = r6p[p];
            float e  = expf(-fabsf(r6 - r5));
            v = (r6 >= r5) ? 1.0f / (e + 1.0f) : e / (1.0f + e);
        }
        sp[i] = v;
    }
    __syncthreads();

    int lx = (threadIdx.x & 15) + 1;
    int ly = (threadIdx.x >> 4) + 1;
    float a = sp[ly * 18 + lx];
    if (a <= THp) return;
    int c = ly * 18 + lx;
    float mx;
    mx = fmaxf(sp[c - 19], sp[c - 18]);
    mx = fmaxf(mx, sp[c - 17]);
    mx = fmaxf(mx, sp[c - 1]);
    mx = fmaxf(mx, sp[c + 1]);
    mx = fmaxf(mx, sp[c + 17]);
    mx = fmaxf(mx, sp[c + 18]);
    mx = fmaxf(mx, sp[c + 19]);
    if (a >= mx) {                                 // a == maxpool(a) semantics
        int p = ((ty0 + ly - 1) << 8) + (tx0 + lx - 1);
        int pos = atomicAdd(&g_ccnt[b], 1);
        if (pos < CAPp) {
            unsigned inv = ~__float_as_uint(a);
            g_ckey[b][pos] = (((unsigned long long)inv) << 32) | (unsigned)p;
        }
    }
}

// ---------------------------------------------------------------------------
// K2: two-level radix select, barrier-lean bitonic sort (warp-shuffle
// sub-stages), junction decode, CSR spatial grid build. Blocks 0..Bp-1 do the
// real work (one per batch); blocks >= Bp zero the remaining 2/3 of the
// output on the otherwise-idle SMs (done before k_match by stream order).
// ---------------------------------------------------------------------------
struct SmemT {
    union {
        int hist[NBINS];                 // histogram (both levels) / scan
        int cnt1[1024];                  // cell counts, then fill cursors
    } u;
    unsigned long long sel[SELC];
    int warpsum[32];
    int sT, sCum, sSel;
};

// Find smallest bin T with cumulative >= target over sm.u.hist (4 bins/thread).
// Writes sm.sT (bin) and sm.sCum (inclusive cumulative through T).
// Caller must __syncthreads() before reading sm.sT / sm.sCum.
__device__ __forceinline__ void scan_find_bin(SmemT& sm, int target,
                                              int tid, int lane, int wid) {
    int base = tid * 4;
    int h0 = sm.u.hist[base], h1 = sm.u.hist[base+1];
    int h2 = sm.u.hist[base+2], h3 = sm.u.hist[base+3];
    int tot = h0 + h1 + h2 + h3;
    int inc = tot;
    #pragma unroll
    for (int d = 1; d < 32; d <<= 1) {
        int n = __shfl_up_sync(0xffffffffu, inc, d);
        if (lane >= d) inc += n;
    }
    if (lane == 31) sm.warpsum[wid] = inc;
    __syncthreads();
    if (wid == 0) {
        int v = sm.warpsum[lane];
        int i2 = v;
        #pragma unroll
        for (int d = 1; d < 32; d <<= 1) {
            int n = __shfl_up_sync(0xffffffffu, i2, d);
            if (lane >= d) i2 += n;
        }
        sm.warpsum[lane] = i2 - v;   // exclusive warp offsets
    }
    __syncthreads();
    int run = sm.warpsum[wid] + inc - tot;   // exclusive prefix for this thread
    int hh[4] = {h0, h1, h2, h3};
    #pragma unroll
    for (int i = 0; i < 4; i++) {
        run += hh[i];
        if (run >= target && run - hh[i] < target) { sm.sT = base + i; sm.sCum = run; }
    }
}

__device__ __forceinline__ unsigned long long bx(unsigned long long v, int j) {
    return __shfl_xor_sync(0xffffffffu, v, j);
}

__global__ void __launch_bounds__(1024) k_topk(const float* __restrict__ raw,
                                               float4* __restrict__ zdst) {
    __shared__ SmemT sm;
    if (blockIdx.x >= Bp) {                        // zeroing blocks: [ZC4, ZERO4)
        int base = ZC4 + (blockIdx.x - Bp) * 4096 + threadIdx.x;
        float4 z = make_float4(0.f, 0.f, 0.f, 0.f);
        zdst[base] = z;
        zdst[base + 1024] = z;
        zdst[base + 2048] = z;
        zdst[base + 3072] = z;
        return;
    }
    int b = blockIdx.x;
    int tid = threadIdx.x;
    int lane = tid & 31, wid = tid >> 5;
    int cnt = min(g_ccnt[b], CAPp);
    int target = min(Jp, cnt);

    if (cnt == 0) {   // defensive; never hit with this data
        if (tid < Jp) g_juncs[b][tid] = make_float2(0.f, 0.f);
        g_cellStart[b][tid] = 0;
        if (tid == 0) { g_cellStart[b][1024] = 0; g_nvalid[b] = 0; }
        return;
    }

    // --- level 1: histogram over key bits [52:64) ---
    for (int i = tid; i < NBINS; i += 1024) sm.u.hist[i] = 0;
    __syncthreads();
    for (int i = tid; i < cnt; i += 1024)
        atomicAdd(&sm.u.hist[(int)(g_ckey[b][i] >> 52)], 1);
    __syncthreads();
    scan_find_bin(sm, target, tid, lane, wid);
    __syncthreads();
    int T1 = sm.sT;
    int cntBefore = sm.sCum - sm.u.hist[T1];   // keys strictly below bin T1
    __syncthreads();                           // all reads done before reuse

    // --- level 2: histogram of bin-T1 keys over bits [40:52) ---
    for (int i = tid; i < NBINS; i += 1024) sm.u.hist[i] = 0;
    if (tid == 0) sm.sSel = 0;
    __syncthreads();
    for (int i = tid; i < cnt; i += 1024) {
        unsigned long long key = g_ckey[b][i];
        if ((int)(key >> 52) == T1)
            atomicAdd(&sm.u.hist[(int)(key >> 40) & 0xFFF], 1);
    }
    __syncthreads();
    scan_find_bin(sm, target - cntBefore, tid, lane, wid);
    __syncthreads();
    int T2 = sm.sT;
    int S = min(cntBefore + sm.sCum, SELC);    // S ~= target + few collisions

    // --- compact the selected superset ---
    for (int i = tid; i < cnt; i += 1024) {
        unsigned long long key = g_ckey[b][i];
        int b1 = (int)(key >> 52);
        if (b1 < T1 || (b1 == T1 && ((int)(key >> 40) & 0xFFF) <= T2)) {
            int pos = atomicAdd(&sm.sSel, 1);
            if (pos < SELC) sm.sel[pos] = key;
        }
    }
    __syncthreads();
    if (tid >= S) sm.sel[tid] = ~0ULL;        // pad to M=1024
    __syncthreads();

    // --- bitonic sort of M=1024, barrier-lean:
    //     stages k=2..32 fully in registers (intra-warp shuffles);
    //     stages k>=64: smem passes for j>=32, 5-shuffle register tail.
    //     Same comparison network as a plain bitonic sort -> identical order.
    {
        unsigned long long e = sm.sel[tid];
        #pragma unroll
        for (int k = 2; k <= 32; k <<= 1) {
            #pragma unroll
            for (int j = k >> 1; j > 0; j >>= 1) {
                unsigned long long o = bx(e, j);
                bool takeMin = ((tid & k) == 0) == ((tid & j) == 0);
                e = ((e < o) == takeMin) ? e : o;
            }
        }
        sm.sel[tid] = e;
        __syncthreads();
        for (int k = 64; k <= 1024; k <<= 1) {
            for (int j = k >> 1; j >= 32; j >>= 1) {
                int ixj = tid ^ j;
                if (ixj > tid) {
                    unsigned long long a = sm.sel[tid], c2 = sm.sel[ixj];
                    bool up = ((tid & k) == 0);
                    if ((a > c2) == up) { sm.sel[tid] = c2; sm.sel[ixj] = a; }
                }
                __syncthreads();
            }
            e = sm.sel[tid];
            #pragma unroll
            for (int j = 16; j > 0; j >>= 1) {
                unsigned long long o = bx(e, j);
                bool takeMin = ((tid & k) == 0) == ((tid & j) == 0);
                e = ((e < o) == takeMin) ? e : o;
            }
            sm.sel[tid] = e;
            __syncthreads();
        }
    }

    int nv = target;
    if (tid == 0) g_nvalid[b] = nv;

    // --- decode junction tid (one thread per junction) ---
    float qx = 0.f, qy = 0.f;
    int myCell = -1;
    const float* rb = raw + (size_t)b * 9 * HWp;
    if (tid < Jp) {
        if (tid < nv) {
            unsigned long long key = sm.sel[tid];
            int p = (int)(key & 0xFFFFFFFFu);
            float offx = sigf(rb[7 * HWp + p]) - 0.5f;
            float offy = sigf(rb[8 * HWp + p]) - 0.5f;
            qx = (float)(p & 255) + offx + 0.5f;
            qy = (float)(p >> 8) + offy + 0.5f;
            myCell = (((int)qy >> 3) << 5) + ((int)qx >> 3);   // 32x32 cells of 8px
        }
        g_juncs[b][tid] = make_float2(qx, qy);
    }
    __syncthreads();          // done with sel/hist before reuse

    // --- build CSR cell grid ---
    sm.u.cnt1[tid] = 0;
    __syncthreads();
    if (myCell >= 0) atomicAdd(&sm.u.cnt1[myCell], 1);
    __syncthreads();
    int v = sm.u.cnt1[tid];
    int inc2 = v;
    #pragma unroll
    for (int d = 1; d < 32; d <<= 1) {
        int n = __shfl_up_sync(0xffffffffu, inc2, d);
        if (lane >= d) inc2 += n;
    }
    if (lane == 31) sm.warpsum[wid] = inc2;
    __syncthreads();
    if (wid == 0) {
        int vv = sm.warpsum[lane];
        int i2 = vv;
        #pragma unroll
        for (int d = 1; d < 32; d <<= 1) {
            int n = __shfl_up_sync(0xffffffffu, i2, d);
            if (lane >= d) i2 += n;
        }
        sm.warpsum[lane] = i2 - vv;
    }
    __syncthreads();
    int excl = sm.warpsum[wid] + inc2 - v;
    g_cellStart[b][tid] = excl;
    if (tid == 1023) g_cellStart[b][1024] = excl + v;   // == nv
    __syncthreads();
    sm.u.cnt1[tid] = excl;     // fill cursors
    __syncthreads();
    if (myCell >= 0) {
        int pos = atomicAdd(&sm.u.cnt1[myCell], 1);
        g_gpos[b][pos] = make_float2(qx, qy);
        g_gidx[b][pos] = tid;
    }
}

// ---------------------------------------------------------------------------
// Pruned nearest-junction search: any junction with d^2 < 10 lies within the
// cell window [e-sqrt(10), e+sqrt(10)]. (d, idx) lexicographic min reproduces
// the reference argmin first-index tie-break exactly.
// ---------------------------------------------------------------------------
__device__ __forceinline__ void nearest(int b, float ex, float ey,
                                        float& bd, int& bi) {
    int cx0 = ((int)fmaxf(ex - RADp, 0.0f)) >> 3;
    int cx1 = ((int)fminf(ex + RADp, 255.0f)) >> 3;
    int cy0 = ((int)fmaxf(ey - RADp, 0.0f)) >> 3;
    int cy1 = ((int)fminf(ey + RADp, 255.0f)) >> 3;
    for (int cy = cy0; cy <= cy1; cy++) {
        for (int cx = cx0; cx <= cx1; cx++) {
            int c = (cy << 5) + cx;
            int s = __ldg(&g_cellStart[b][c]);
            int e = __ldg(&g_cellStart[b][c + 1]);
            for (int k = s; k < e; k++) {
                float2 q = __ldg(&g_gpos[b][k]);
                int idx  = __ldg(&g_gidx[b][k]);
                float dx = ex - q.x, dy = ey - q.y;
                float d = fmaf(dy, dy, dx * dx);
                if (d < bd || (d == bd && idx < bi)) { bd = d; bi = idx; }
            }
        }
    }
}

// ---------------------------------------------------------------------------
// Scatter one matched line. First toucher (atomicAdd returns 0) also writes
// lines_adj[g] — value depends only on g, so winner identity is irrelevant.
// ---------------------------------------------------------------------------
__device__ __forceinline__ void scatter(int b, float l0, float l1, float l2, float l3,
                                        float bd1, int bi1, float bd2, int bi2,
                                        float4* __restrict__ lines,
                                        float* __restrict__ counts,
                                        float* __restrict__ support) {
    if (bd1 < J2Lp && bd2 < J2Lp && bi1 != bi2) {
        int imin = min(bi1, bi2), imax = max(bi1, bi2);
        int g = b * JJp + imin * Jp + imax;
        float old = atomicAdd(&counts[g], 1.0f);
        atomicAdd(&support[(size_t)g * 4 + 0], l0);
        atomicAdd(&support[(size_t)g * 4 + 1], l1);
        atomicAdd(&support[(size_t)g * 4 + 2], l2);
        atomicAdd(&support[(size_t)g * 4 + 3], l3);
        if (old == 0.0f) {
            float2 A  = g_juncs[b][imin];
            float2 Bq = g_juncs[b][imax];
            lines[g] = make_float4(A.x, A.y, Bq.x, Bq.y);
        }
    }
}

// ---------------------------------------------------------------------------
// K3: decode two pixels per thread with interleaved (independent) trig chains
// for ILP, then the four pruned nearest searches, then scatters.
// ---------------------------------------------------------------------------
__global__ void __launch_bounds__(256) k_match(const float* __restrict__ raw,
                                               float4* __restrict__ lines,
                                               float* __restrict__ counts,
                                               float* __restrict__ support) {
    int b = blockIdx.y;
    if (b == 0 && blockIdx.x == 0 && threadIdx.x == 0) {
        g_ccnt[0] = 0; g_ccnt[1] = 0;    // reset for next replay (topk consumed it)
    }
    const float* rb = raw + (size_t)b * 9 * HWp;
    int pA = blockIdx.x * 512 + threadIdx.x;
    int pB = pA + 256;

    // --- interleaved decode of both pixels (independent chains -> ILP) ---
    float a0 = rb[pA],           b0 = rb[pB];
    float a1 = rb[HWp + pA],     b1 = rb[HWp + pB];
    float a2 = rb[2 * HWp + pA], b2 = rb[2 * HWp + pB];
    float a3 = rb[3 * HWp + pA], b3 = rb[3 * HWp + pB];

    float amd0 = sigf(a0), bmd0 = sigf(b0);
    float amd1 = sigf(a1), bmd1 = sigf(b1);
    float amd2 = sigf(a2), bmd2 = sigf(b2);
    float ad   = sigf(a3), bdd  = sigf(b3);

    float ath = (amd0 - 0.5f) * 6.28318530717958647692f;
    float bth = (bmd0 - 0.5f) * 6.28318530717958647692f;
    float acs, ass, bcs, bss;
    sincosf(ath, &ass, &acs);
    sincosf(bth, &bss, &bcs);
    float ayst = tanf(amd1 * 1.57079632679489661923f);
    float byst = tanf(bmd1 * 1.57079632679489661923f);
    float ayed = tanf(-amd2 * 1.57079632679489661923f);
    float byed = tanf(-bmd2 * 1.57079632679489661923f);
    float ads = ad * SCALEp, bds = bdd * SCALEp;

    float ax0 = (float)(pA & 255), ay0 = (float)(pA >> 8);
    float bx0 = (float)(pB & 255), by0 = (float)(pB >> 8);

    float al0 = fminf(fmaxf((acs - ass * ayst) * ads + ax0, 0.0f), 255.0f);
    float al1 = fminf(fmaxf((ass + acs * ayst) * ads + ay0, 0.0f), 255.0f);
    float al2 = fminf(fmaxf((acs - ass * ayed) * ads + ax0, 0.0f), 255.0f);
    float al3 = fminf(fmaxf((ass + acs * ayed) * ads + ay0, 0.0f), 255.0f);
    float bl0 = fminf(fmaxf((bcs - bss * byst) * bds + bx0, 0.0f), 255.0f);
    float bl1 = fminf(fmaxf((bss + bcs * byst) * bds + by0, 0.0f), 255.0f);
    float bl2 = fminf(fmaxf((bcs - bss * byed) * bds + bx0, 0.0f), 255.0f);
    float bl3 = fminf(fmaxf((bss + bcs * byed) * bds + by0, 0.0f), 255.0f);

    // --- nearest searches ---
    float abd1 = 1e30f, abd2 = 1e30f, bbd1 = 1e30f, bbd2 = 1e30f;
    int   abi1 = Jp, abi2 = Jp, bbi1 = Jp, bbi2 = Jp;
    nearest(b, al0, al1, abd1, abi1);
    nearest(b, al2, al3, abd2, abi2);
    nearest(b, bl0, bl1, bbd1, bbi1);
    nearest(b, bl2, bl3, bbd2, bbi2);

    scatter(b, al0, al1, al2, al3, abd1, abi1, abd2, abi2, lines, counts, support);
    scatter(b, bl0, bl1, bl2, bl3, bbd1, bbi1, bbd2, bbi2, lines, counts, support);
}

// ---------------------------------------------------------------------------
// Launch. Output layout: lines_adj [B*JJ*4] | counts [B*JJ] | support [B*JJ*4]
// ---------------------------------------------------------------------------
extern "C" void kernel_launch(void* const* d_in, const int* in_sizes, int n_in,
                              void* d_out, int out_size) {
    const float* raw = (const float*)d_in[0];
    float* out = (float*)d_out;
    float* counts  = out + (size_t)Bp * JJp * 4;
    float* support = counts + (size_t)Bp * JJp;

    dim3 gcand(256 + ZBLKC, Bp);
    k_cand_zero<<<gcand, 256>>>(raw, (float4*)out);   // zeroes 1/3 of output
    k_topk<<<Bp + ZBLKT, 1024>>>(raw, (float4*)out);  // zeroes the other 2/3
    dim3 gmatch(HWp / 512, Bp);
    k_match<<<gmatch, 256>>>(raw, (float4*)out, counts, support);
}

// round 9
// speedup vs baseline: 3.3083x; 1.0117x over previous
#include <cuda_runtime.h>
#include <stdint.h>

// Problem constants
#define HWp   65536      // 256*256
#define Bp    2
#define Jp    512
#define JJp   (Jp*Jp)    // 262144
#define CAPp  16384      // candidate capacity per batch (expected ~7.3k)
#define THp   0.008f
#define J2Lp  10.0f
#define SCALEp 5.0f
#define NBINS 4096       // histogram bins (12 bits per level)
#define SELC  1024       // compaction capacity (S ~= 515 after 2-level select)
#define RADp  3.16227766f // sqrt(10): max distance that can ever match
#define ZERO4 ((Bp*JJp*9)/4)  // float4 count of the ENTIRE output region = 1179648
#define TILES 64              // 32x32-pixel NMS tiles per batch (8x8)
#define ZBLKC 384             // zero blocks per batch in k_cand (512 float4 each)
#define ZC4   (Bp*ZBLKC*512)  // float4s zeroed by k_cand = 393216
#define ZBLKT 192             // zero blocks in k_topk (4096 float4 each) = 786432

// Scratch (static device globals — no allocation allowed)
__device__ unsigned long long  g_ckey[Bp][CAPp];
__device__ int                 g_ccnt[Bp];        // zero-init; reset by k_match
__device__ int                 g_nvalid[Bp];
__device__ float2              g_juncs[Bp][Jp];
__device__ int                 g_cellStart[Bp][1025];  // CSR over 32x32 cells of 8px
__device__ float4              g_gpack[Bp][Jp];        // (x, y, idx_bits, 0) cell order

__device__ __forceinline__ float sigf(float x) { return 1.0f / (1.0f + expf(-x)); }

// ---------------------------------------------------------------------------
// K1: fused softmax-prob + 3x3 NMS + candidate append. 32x32-pixel tiles with
// a 34x34 halo in smem; 4 pixels/thread for ILP on the latency-bound expf
// chains. Extra blocks zero 1/3 of the output (rest rides on k_topk).
// prob = softmax(raw[:,5:7],axis=1)[:,1] with ONE expf (one of the two
// exponentials is exactly 1.0f after max-subtraction) -> bit-identical.
// key = (~float_bits(score) << 32) | pixel -> ascending == score desc,
// pixel-index asc on ties (matches jax.lax.top_k ordering).
// ---------------------------------------------------------------------------
__global__ void __launch_bounds__(256) k_cand_zero(const float* __restrict__ raw,
                                                   float4* __restrict__ zdst) {
    int b = blockIdx.y;
    if (blockIdx.x >= TILES) {                     // zeroing blocks: [0, ZC4)
        int zi = ((blockIdx.x - TILES) + b * ZBLKC) * 512 + threadIdx.x;
        float4 z = make_float4(0.f, 0.f, 0.f, 0.f);
        zdst[zi] = z;
        zdst[zi + 256] = z;
        return;
    }
    __shared__ float sp[34 * 34];                  // 32x32 tile + 1px halo
    int tile = blockIdx.x;
    int tx0 = (tile & 7) << 5;
    int ty0 = (tile >> 3) << 5;
    const float* r5p = raw + (size_t)b * 9 * HWp + 5 * HWp;
    const float* r6p = raw + (size_t)b * 9 * HWp + 6 * HWp;

    // halo fill: 1156 entries, 5 independent iterations/thread (ILP)
    #pragma unroll
    for (int it = 0; it < 5; it++) {
        int i = threadIdx.x + it * 256;
        if (i < 34 * 34) {
            int hx = tx0 - 1 + (i % 34);
            int hy = ty0 - 1 + (i / 34);
            float v = -1.0f;                       // OOB: below any prob (>0)
            if ((unsigned)hx < 256u && (unsigned)hy < 256u) {
                int p = (hy << 8) + hx;
                float r5 = r5p[p];
                float r6 = r6p[p];
                float e  = expf(-fabsf(r6 - r5));
                v = (r6 >= r5) ? 1.0f / (e + 1.0f) : e / (1.0f + e);
            }
            sp[i] = v;
        }
    }
    __syncthreads();

    // NMS: 4 pixels per thread (consecutive rows, same column)
    int lx = threadIdx.x & 31;
    int ly0 = (threadIdx.x >> 5) << 2;
    #pragma unroll
    for (int r = 0; r < 4; r++) {
        int ly = ly0 + r;
        int c = (ly + 1) * 34 + (lx + 1);
        float a = sp[c];
        if (a <= THp) continue;
        float mx;
        mx = fmaxf(sp[c - 35], sp[c - 34]);
        mx = fmaxf(mx, sp[c - 33]);
        mx = fmaxf(mx, sp[c - 1]);
        mx = fmaxf(mx, sp[c + 1]);
        mx = fmaxf(mx, sp[c + 33]);
        mx = fmaxf(mx, sp[c + 34]);
        mx = fmaxf(mx, sp[c + 35]);
        if (a >= mx) {                             // a == maxpool(a) semantics
            int p = ((ty0 + ly) << 8) + (tx0 + lx);
            int pos = atomicAdd(&g_ccnt[b], 1);
            if (pos < CAPp) {
                unsigned inv = ~__float_as_uint(a);
                g_ckey[b][pos] = (((unsigned long long)inv) << 32) | (unsigned)p;
            }
        }
    }
}

// ---------------------------------------------------------------------------
// K2: two-level radix select, barrier-lean bitonic sort (warp-shuffle
// sub-stages), junction decode, CSR spatial grid build. Blocks 0..Bp-1 do the
// real work; blocks >= Bp zero the remaining 2/3 of the output on the
// otherwise-idle SMs (done before k_match by stream order).
// ---------------------------------------------------------------------------
struct SmemT {
    union {
        int hist[NBINS];                 // histogram (both levels) / scan
        int cnt1[1024];                  // cell counts, then fill cursors
    } u;
    unsigned long long sel[SELC];
    int warpsum[32];
    int sT, sCum, sSel;
};

// Find smallest bin T with cumulative >= target over sm.u.hist (4 bins/thread).
// Writes sm.sT (bin) and sm.sCum (inclusive cumulative through T).
// Caller must __syncthreads() before reading sm.sT / sm.sCum.
__device__ __forceinline__ void scan_find_bin(SmemT& sm, int target,
                                              int tid, int lane, int wid) {
    int base = tid * 4;
    int h0 = sm.u.hist[base], h1 = sm.u.hist[base+1];
    int h2 = sm.u.hist[base+2], h3 = sm.u.hist[base+3];
    int tot = h0 + h1 + h2 + h3;
    int inc = tot;
    #pragma unroll
    for (int d = 1; d < 32; d <<= 1) {
        int n = __shfl_up_sync(0xffffffffu, inc, d);
        if (lane >= d) inc += n;
    }
    if (lane == 31) sm.warpsum[wid] = inc;
    __syncthreads();
    if (wid == 0) {
        int v = sm.warpsum[lane];
        int i2 = v;
        #pragma unroll
        for (int d = 1; d < 32; d <<= 1) {
            int n = __shfl_up_sync(0xffffffffu, i2, d);
            if (lane >= d) i2 += n;
        }
        sm.warpsum[lane] = i2 - v;   // exclusive warp offsets
    }
    __syncthreads();
    int run = sm.warpsum[wid] + inc - tot;   // exclusive prefix for this thread
    int hh[4] = {h0, h1, h2, h3};
    #pragma unroll
    for (int i = 0; i < 4; i++) {
        run += hh[i];
        if (run >= target && run - hh[i] < target) { sm.sT = base + i; sm.sCum = run; }
    }
}

__device__ __forceinline__ unsigned long long bx(unsigned long long v, int j) {
    return __shfl_xor_sync(0xffffffffu, v, j);
}

__global__ void __launch_bounds__(1024) k_topk(const float* __restrict__ raw,
                                               float4* __restrict__ zdst) {
    __shared__ SmemT sm;
    if (blockIdx.x >= Bp) {                        // zeroing blocks: [ZC4, ZERO4)
        int base = ZC4 + (blockIdx.x - Bp) * 4096 + threadIdx.x;
        float4 z = make_float4(0.f, 0.f, 0.f, 0.f);
        zdst[base] = z;
        zdst[base + 1024] = z;
        zdst[base + 2048] = z;
        zdst[base + 3072] = z;
        return;
    }
    int b = blockIdx.x;
    int tid = threadIdx.x;
    int lane = tid & 31, wid = tid >> 5;
    int cnt = min(g_ccnt[b], CAPp);
    int target = min(Jp, cnt);

    if (cnt == 0) {   // defensive; never hit with this data
        if (tid < Jp) g_juncs[b][tid] = make_float2(0.f, 0.f);
        g_cellStart[b][tid] = 0;
        if (tid == 0) { g_cellStart[b][1024] = 0; g_nvalid[b] = 0; }
        return;
    }

    // --- level 1: histogram over key bits [52:64) ---
    for (int i = tid; i < NBINS; i += 1024) sm.u.hist[i] = 0;
    __syncthreads();
    for (int i = tid; i < cnt; i += 1024)
        atomicAdd(&sm.u.hist[(int)(g_ckey[b][i] >> 52)], 1);
    __syncthreads();
    scan_find_bin(sm, target, tid, lane, wid);
    __syncthreads();
    int T1 = sm.sT;
    int cntBefore = sm.sCum - sm.u.hist[T1];   // keys strictly below bin T1
    __syncthreads();                           // all reads done before reuse

    // --- level 2: histogram of bin-T1 keys over bits [40:52) ---
    for (int i = tid; i < NBINS; i += 1024) sm.u.hist[i] = 0;
    if (tid == 0) sm.sSel = 0;
    __syncthreads();
    for (int i = tid; i < cnt; i += 1024) {
        unsigned long long key = g_ckey[b][i];
        if ((int)(key >> 52) == T1)
            atomicAdd(&sm.u.hist[(int)(key >> 40) & 0xFFF], 1);
    }
    __syncthreads();
    scan_find_bin(sm, target - cntBefore, tid, lane, wid);
    __syncthreads();
    int T2 = sm.sT;
    int S = min(cntBefore + sm.sCum, SELC);    // S ~= target + few collisions

    // --- compact the selected superset ---
    for (int i = tid; i < cnt; i += 1024) {
        unsigned long long key = g_ckey[b][i];
        int b1 = (int)(key >> 52);
        if (b1 < T1 || (b1 == T1 && ((int)(key >> 40) & 0xFFF) <= T2)) {
            int pos = atomicAdd(&sm.sSel, 1);
            if (pos < SELC) sm.sel[pos] = key;
        }
    }
    __syncthreads();
    if (tid >= S) sm.sel[tid] = ~0ULL;        // pad to M=1024
    __syncthreads();

    // --- bitonic sort of M=1024, barrier-lean:
    //     stages k=2..32 fully in registers (intra-warp shuffles);
    //     stages k>=64: smem passes for j>=32, 5-shuffle register tail.
    //     Same comparison network as a plain bitonic sort -> identical order.
    {
        unsigned long long e = sm.sel[tid];
        #pragma unroll
        for (int k = 2; k <= 32; k <<= 1) {
            #pragma unroll
            for (int j = k >> 1; j > 0; j >>= 1) {
                unsigned long long o = bx(e, j);
                bool takeMin = ((tid & k) == 0) == ((tid & j) == 0);
                e = ((e < o) == takeMin) ? e : o;
            }
        }
        sm.sel[tid] = e;
        __syncthreads();
        for (int k = 64; k <= 1024; k <<= 1) {
            for (int j = k >> 1; j >= 32; j >>= 1) {
                int ixj = tid ^ j;
                if (ixj > tid) {
                    unsigned long long a = sm.sel[tid], c2 = sm.sel[ixj];
                    bool up = ((tid & k) == 0);
                    if ((a > c2) == up) { sm.sel[tid] = c2; sm.sel[ixj] = a; }
                }
                __syncthreads();
            }
            e = sm.sel[tid];
            #pragma unroll
            for (int j = 16; j > 0; j >>= 1) {
                unsigned long long o = bx(e, j);
                bool takeMin = ((tid & k) == 0) == ((tid & j) == 0);
                e = ((e < o) == takeMin) ? e : o;
            }
            sm.sel[tid] = e;
            __syncthreads();
        }
    }

    int nv = target;
    if (tid == 0) g_nvalid[b] = nv;

    // --- decode junction tid (one thread per junction) ---
    float qx = 0.f, qy = 0.f;
    int myCell = -1;
    const float* rb = raw + (size_t)b * 9 * HWp;
    if (tid < Jp) {
        if (tid < nv) {
            unsigned long long key = sm.sel[tid];
            int p = (int)(key & 0xFFFFFFFFu);
            float offx = sigf(rb[7 * HWp + p]) - 0.5f;
            float offy = sigf(rb[8 * HWp + p]) - 0.5f;
            qx = (float)(p & 255) + offx + 0.5f;
            qy = (float)(p >> 8) + offy + 0.5f;
            myCell = (((int)qy >> 3) << 5) + ((int)qx >> 3);   // 32x32 cells of 8px
        }
        g_juncs[b][tid] = make_float2(qx, qy);
    }
    __syncthreads();          // done with sel/hist before reuse

    // --- build CSR cell grid ---
    sm.u.cnt1[tid] = 0;
    __syncthreads();
    if (myCell >= 0) atomicAdd(&sm.u.cnt1[myCell], 1);
    __syncthreads();
    int v = sm.u.cnt1[tid];
    int inc2 = v;
    #pragma unroll
    for (int d = 1; d < 32; d <<= 1) {
        int n = __shfl_up_sync(0xffffffffu, inc2, d);
        if (lane >= d) inc2 += n;
    }
    if (lane == 31) sm.warpsum[wid] = inc2;
    __syncthreads();
    if (wid == 0) {
        int vv = sm.warpsum[lane];
        int i2 = vv;
        #pragma unroll
        for (int d = 1; d < 32; d <<= 1) {
            int n = __shfl_up_sync(0xffffffffu, i2, d);
            if (lane >= d) i2 += n;
        }
        sm.warpsum[lane] = i2 - vv;
    }
    __syncthreads();
    int excl = sm.warpsum[wid] + inc2 - v;
    g_cellStart[b][tid] = excl;
    if (tid == 1023) g_cellStart[b][1024] = excl + v;   // == nv
    __syncthreads();
    sm.u.cnt1[tid] = excl;     // fill cursors
    __syncthreads();
    if (myCell >= 0) {
        int pos = atomicAdd(&sm.u.cnt1[myCell], 1);
        g_gpack[b][pos] = make_float4(qx, qy, __int_as_float(tid), 0.f);
    }
}

// ---------------------------------------------------------------------------
// Pruned nearest-junction search with row-contiguous CSR scan: cells
// cx0..cx1 of one row are adjacent in CSR order, so one contiguous range per
// row — same elements, same ascending order as per-cell loops. Packed float4
// (x, y, idx_bits) = one LDG.128 per junction. (d, idx) lexicographic min
// reproduces the reference argmin first-index tie-break exactly.
// ---------------------------------------------------------------------------
__device__ __forceinline__ void nearest(const float4* __restrict__ gp,
                                        const int* __restrict__ cs,
                                        float ex, float ey,
                                        float& bd, int& bi) {
    int cx0 = ((int)fmaxf(ex - RADp, 0.0f)) >> 3;
    int cx1 = ((int)fminf(ex + RADp, 255.0f)) >> 3;
    int cy0 = ((int)fmaxf(ey - RADp, 0.0f)) >> 3;
    int cy1 = ((int)fminf(ey + RADp, 255.0f)) >> 3;
    for (int cy = cy0; cy <= cy1; cy++) {
        int s = __ldg(&cs[(cy << 5) + cx0]);
        int e = __ldg(&cs[(cy << 5) + cx1 + 1]);
        for (int k = s; k < e; k++) {
            float4 q = __ldg(&gp[k]);
            int idx  = __float_as_int(q.z);
            float dx = ex - q.x, dy = ey - q.y;
            float d = fmaf(dy, dy, dx * dx);
            if (d < bd || (d == bd && idx < bi)) { bd = d; bi = idx; }
        }
    }
}

// ---------------------------------------------------------------------------
// Scatter one matched line. First toucher (atomicAdd returns 0) also writes
// lines_adj[g] — value depends only on g, so winner identity is irrelevant.
// ---------------------------------------------------------------------------
__device__ __forceinline__ void scatter(int b, float l0, float l1, float l2, float l3,
                                        float bd1, int bi1, float bd2, int bi2,
                                        float4* __restrict__ lines,
                                        float* __restrict__ counts,
                                        float* __restrict__ support) {
    if (bd1 < J2Lp && bd2 < J2Lp && bi1 != bi2) {
        int imin = min(bi1, bi2), imax = max(bi1, bi2);
        int g = b * JJp + imin * Jp + imax;
        float old = atomicAdd(&counts[g], 1.0f);
        atomicAdd(&support[(size_t)g * 4 + 0], l0);
        atomicAdd(&support[(size_t)g * 4 + 1], l1);
        atomicAdd(&support[(size_t)g * 4 + 2], l2);
        atomicAdd(&support[(size_t)g * 4 + 3], l3);
        if (old == 0.0f) {
            float2 A  = g_juncs[b][imin];
            float2 Bq = g_juncs[b][imax];
            lines[g] = make_float4(A.x, A.y, Bq.x, Bq.y);
        }
    }
}

// ---------------------------------------------------------------------------
// K3: decode two pixels per thread with interleaved (independent) trig chains
// for ILP, then the four pruned nearest searches, then scatters.
// ---------------------------------------------------------------------------
__global__ void __launch_bounds__(256) k_match(const float* __restrict__ raw,
                                               float4* __restrict__ lines,
                                               float* __restrict__ counts,
                                               float* __restrict__ support) {
    int b = blockIdx.y;
    if (b == 0 && blockIdx.x == 0 && threadIdx.x == 0) {
        g_ccnt[0] = 0; g_ccnt[1] = 0;    // reset for next replay (topk consumed it)
    }
    const float* rb = raw + (size_t)b * 9 * HWp;
    const float4* gp = g_gpack[b];
    const int* cs = g_cellStart[b];
    int pA = blockIdx.x * 512 + threadIdx.x;
    int pB = pA + 256;

    // --- interleaved decode of both pixels (independent chains -> ILP) ---
    float a0 = rb[pA],           b0 = rb[pB];
    float a1 = rb[HWp + pA],     b1 = rb[HWp + pB];
    float a2 = rb[2 * HWp + pA], b2 = rb[2 * HWp + pB];
    float a3 = rb[3 * HWp + pA], b3 = rb[3 * HWp + pB];

    float amd0 = sigf(a0), bmd0 = sigf(b0);
    float amd1 = sigf(a1), bmd1 = sigf(b1);
    float amd2 = sigf(a2), bmd2 = sigf(b2);
    float ad   = sigf(a3), bdd  = sigf(b3);

    float ath = (amd0 - 0.5f) * 6.28318530717958647692f;
    float bth = (bmd0 - 0.5f) * 6.28318530717958647692f;
    float acs, ass, bcs, bss;
    sincosf(ath, &ass, &acs);
    sincosf(bth, &bss, &bcs);
    float ayst = tanf(amd1 * 1.57079632679489661923f);
    float byst = tanf(bmd1 * 1.57079632679489661923f);
    float ayed = tanf(-amd2 * 1.57079632679489661923f);
    float byed = tanf(-bmd2 * 1.57079632679489661923f);
    float ads = ad * SCALEp, bds = bdd * SCALEp;

    float ax0 = (float)(pA & 255), ay0 = (float)(pA >> 8);
    float bx0 = (float)(pB & 255), by0 = (float)(pB >> 8);

    float al0 = fminf(fmaxf((acs - ass * ayst) * ads + ax0, 0.0f), 255.0f);
    float al1 = fminf(fmaxf((ass + acs * ayst) * ads + ay0, 0.0f), 255.0f);
    float al2 = fminf(fmaxf((acs - ass * ayed) * ads + ax0, 0.0f), 255.0f);
    float al3 = fminf(fmaxf((ass + acs * ayed) * ads + ay0, 0.0f), 255.0f);
    float bl0 = fminf(fmaxf((bcs - bss * byst) * bds + bx0, 0.0f), 255.0f);
    float bl1 = fminf(fmaxf((bss + bcs * byst) * bds + by0, 0.0f), 255.0f);
    float bl2 = fminf(fmaxf((bcs - bss * byed) * bds + bx0, 0.0f), 255.0f);
    float bl3 = fminf(fmaxf((bss + bcs * byed) * bds + by0, 0.0f), 255.0f);

    // --- nearest searches ---
    float abd1 = 1e30f, abd2 = 1e30f, bbd1 = 1e30f, bbd2 = 1e30f;
    int   abi1 = Jp, abi2 = Jp, bbi1 = Jp, bbi2 = Jp;
    nearest(gp, cs, al0, al1, abd1, abi1);
    nearest(gp, cs, al2, al3, abd2, abi2);
    nearest(gp, cs, bl0, bl1, bbd1, bbi1);
    nearest(gp, cs, bl2, bl3, bbd2, bbi2);

    scatter(b, al0, al1, al2, al3, abd1, abi1, abd2, abi2, lines, counts, support);
    scatter(b, bl0, bl1, bl2, bl3, bbd1, bbi1, bbd2, bbi2, lines, counts, support);
}

// ---------------------------------------------------------------------------
// Launch. Output layout: lines_adj [B*JJ*4] | counts [B*JJ] | support [B*JJ*4]
// ---------------------------------------------------------------------------
extern "C" void kernel_launch(void* const* d_in, const int* in_sizes, int n_in,
                              void* d_out, int out_size) {
    const float* raw = (const float*)d_in[0];
    float* out = (float*)d_out;
    float* counts  = out + (size_t)Bp * JJp * 4;
    float* support = counts + (size_t)Bp * JJp;

    dim3 gcand(TILES + ZBLKC, Bp);
    k_cand_zero<<<gcand, 256>>>(raw, (float4*)out);   // zeroes 1/3 of output
    k_topk<<<Bp + ZBLKT, 1024>>>(raw, (float4*)out);  // zeroes the other 2/3
    dim3 gmatch(HWp / 512, Bp);
    k_match<<<gmatch, 256>>>(raw, (float4*)out, counts, support);
}

// round 11
// speedup vs baseline: 3.4923x; 1.0556x over previous
#include <cuda_runtime.h>
#include <stdint.h>

// Problem constants
#define HWp   65536      // 256*256
#define Bp    2
#define Jp    512
#define JJp   (Jp*Jp)    // 262144
#define CAPp  16384      // candidate capacity per batch (expected ~7.3k)
#define THp   0.008f
#define J2Lp  10.0f
#define SCALEp 5.0f
#define NBINS 4096       // histogram bins (12 bits per level)
#define SELC  1024       // compaction capacity (S ~= 515 after 2-level select)
#define RADp  3.16227766f // sqrt(10): max distance that can ever match
#define ZERO4 ((Bp*JJp*9)/4)  // float4 count of the ENTIRE output region = 1179648
#define TILES 64              // 32x32-pixel NMS tiles per batch (8x8)
#define ZBLKC 48              // zero blocks per batch in k_cand (4096 float4 each)
#define ZC4   (Bp*ZBLKC*4096) // float4s zeroed by k_cand = 393216
#define ZBLKT 192             // zero blocks in k_topk (4096 float4 each) = 786432

// Scratch (static device globals — no allocation allowed)
__device__ unsigned long long  g_ckey[Bp][CAPp];
__device__ int                 g_ccnt[Bp];        // zero-init; reset by k_match
__device__ int                 g_nvalid[Bp];
__device__ float2              g_juncs[Bp][Jp];
__device__ int                 g_cellStart[Bp][1025];  // CSR over 32x32 cells of 8px
__device__ float4              g_gpack[Bp][Jp];        // (x, y, idx_bits, 0) cell order

__device__ __forceinline__ float sigf(float x) { return 1.0f / (1.0f + expf(-x)); }

// ---------------------------------------------------------------------------
// K1: fused softmax-prob + 3x3 NMS + candidate append. 32x32-pixel tiles with
// a 34x34 halo in smem; 1024-thread blocks (1 pixel/thread, 32 warps/SM) so
// the latency-bound expf chains are hidden by TLP. Extra blocks zero 1/3 of
// the output (rest rides on k_topk's idle SMs).
// prob = softmax(raw[:,5:7],axis=1)[:,1] with ONE expf (one of the two
// exponentials is exactly 1.0f after max-subtraction) -> bit-identical.
// key = (~float_bits(score) << 32) | pixel -> ascending == score desc,
// pixel-index asc on ties (matches jax.lax.top_k ordering).
// ---------------------------------------------------------------------------
__global__ void __launch_bounds__(1024) k_cand_zero(const float* __restrict__ raw,
                                                    float4* __restrict__ zdst) {
    int b = blockIdx.y;
    if (blockIdx.x >= TILES) {                     // zeroing blocks: [0, ZC4)
        int zi = ((blockIdx.x - TILES) + b * ZBLKC) * 4096 + threadIdx.x;
        float4 z = make_float4(0.f, 0.f, 0.f, 0.f);
        zdst[zi] = z;
        zdst[zi + 1024] = z;
        zdst[zi + 2048] = z;
        zdst[zi + 3072] = z;
        return;
    }
    __shared__ float sp[34 * 34];                  // 32x32 tile + 1px halo
    int tile = blockIdx.x;
    int tx0 = (tile & 7) << 5;
    int ty0 = (tile >> 3) << 5;
    const float* r5p = raw + (size_t)b * 9 * HWp + 5 * HWp;
    const float* r6p = raw + (size_t)b * 9 * HWp + 6 * HWp;

    // halo fill: 1156 entries, 2 iterations of 1024 threads
    #pragma unroll
    for (int it = 0; it < 2; it++) {
        int i = threadIdx.x + it * 1024;
        if (i < 34 * 34) {
            int hx = tx0 - 1 + (i % 34);
            int hy = ty0 - 1 + (i / 34);
            float v = -1.0f;                       // OOB: below any prob (>0)
            if ((unsigned)hx < 256u && (unsigned)hy < 256u) {
                int p = (hy << 8) + hx;
                float r5 = r5p[p];
                float r6 = r6p[p];
                float e  = expf(-fabsf(r6 - r5));
                v = (r6 >= r5) ? 1.0f / (e + 1.0f) : e / (1.0f + e);
            }
            sp[i] = v;
        }
    }
    __syncthreads();

    // NMS: one pixel per thread
    int lx = threadIdx.x & 31;
    int ly = threadIdx.x >> 5;
    int c = (ly + 1) * 34 + (lx + 1);
    float a = sp[c];
    if (a <= THp) return;
    float mx;
    mx = fmaxf(sp[c - 35], sp[c - 34]);
    mx = fmaxf(mx, sp[c - 33]);
    mx = fmaxf(mx, sp[c - 1]);
    mx = fmaxf(mx, sp[c + 1]);
    mx = fmaxf(mx, sp[c + 33]);
    mx = fmaxf(mx, sp[c + 34]);
    mx = fmaxf(mx, sp[c + 35]);
    if (a >= mx) {                                 // a == maxpool(a) semantics
        int p = ((ty0 + ly) << 8) + (tx0 + lx);
        int pos = atomicAdd(&g_ccnt[b], 1);
        if (pos < CAPp) {
            unsigned inv = ~__float_as_uint(a);
            g_ckey[b][pos] = (((unsigned long long)inv) << 32) | (unsigned)p;
        }
    }
}

// ---------------------------------------------------------------------------
// K2: two-level radix select, barrier-lean bitonic sort (warp-shuffle
// sub-stages), junction decode, CSR spatial grid build. Blocks 0..Bp-1 do the
// real work; blocks >= Bp zero the remaining 2/3 of the output on the
// otherwise-idle SMs (done before k_match by stream order).
// ---------------------------------------------------------------------------
struct SmemT {
    union {
        int hist[NBINS];                 // histogram (both levels) / scan
        int cnt1[1024];                  // cell counts, then fill cursors
    } u;
    unsigned long long sel[SELC];
    int warpsum[32];
    int sT, sCum, sSel;
};

// Find smallest bin T with cumulative >= target over sm.u.hist (4 bins/thread).
// Writes sm.sT (bin) and sm.sCum (inclusive cumulative through T).
// Caller must __syncthreads() before reading sm.sT / sm.sCum.
__device__ __forceinline__ void scan_find_bin(SmemT& sm, int target,
                                              int tid, int lane, int wid) {
    int base = tid * 4;
    int h0 = sm.u.hist[base], h1 = sm.u.hist[base+1];
    int h2 = sm.u.hist[base+2], h3 = sm.u.hist[base+3];
    int tot = h0 + h1 + h2 + h3;
    int inc = tot;
    #pragma unroll
    for (int d = 1; d < 32; d <<= 1) {
        int n = __shfl_up_sync(0xffffffffu, inc, d);
        if (lane >= d) inc += n;
    }
    if (lane == 31) sm.warpsum[wid] = inc;
    __syncthreads();
    if (wid == 0) {
        int v = sm.warpsum[lane];
        int i2 = v;
        #pragma unroll
        for (int d = 1; d < 32; d <<= 1) {
            int n = __shfl_up_sync(0xffffffffu, i2, d);
            if (lane >= d) i2 += n;
        }
        sm.warpsum[lane] = i2 - v;   // exclusive warp offsets
    }
    __syncthreads();
    int run = sm.warpsum[wid] + inc - tot;   // exclusive prefix for this thread
    int hh[4] = {h0, h1, h2, h3};
    #pragma unroll
    for (int i = 0; i < 4; i++) {
        run += hh[i];
        if (run >= target && run - hh[i] < target) { sm.sT = base + i; sm.sCum = run; }
    }
}

__device__ __forceinline__ unsigned long long bx(unsigned long long v, int j) {
    return __shfl_xor_sync(0xffffffffu, v, j);
}

__global__ void __launch_bounds__(1024) k_topk(const float* __restrict__ raw,
                                               float4* __restrict__ zdst) {
    __shared__ SmemT sm;
    if (blockIdx.x >= Bp) {                        // zeroing blocks: [ZC4, ZERO4)
        int base = ZC4 + (blockIdx.x - Bp) * 4096 + threadIdx.x;
        float4 z = make_float4(0.f, 0.f, 0.f, 0.f);
        zdst[base] = z;
        zdst[base + 1024] = z;
        zdst[base + 2048] = z;
        zdst[base + 3072] = z;
        return;
    }
    int b = blockIdx.x;
    int tid = threadIdx.x;
    int lane = tid & 31, wid = tid >> 5;
    int cnt = min(g_ccnt[b], CAPp);
    int target = min(Jp, cnt);

    if (cnt == 0) {   // defensive; never hit with this data
        if (tid < Jp) g_juncs[b][tid] = make_float2(0.f, 0.f);
        g_cellStart[b][tid] = 0;
        if (tid == 0) { g_cellStart[b][1024] = 0; g_nvalid[b] = 0; }
        return;
    }

    // --- level 1: histogram over key bits [52:64) ---
    for (int i = tid; i < NBINS; i += 1024) sm.u.hist[i] = 0;
    __syncthreads();
    for (int i = tid; i < cnt; i += 1024)
        atomicAdd(&sm.u.hist[(int)(g_ckey[b][i] >> 52)], 1);
    __syncthreads();
    scan_find_bin(sm, target, tid, lane, wid);
    __syncthreads();
    int T1 = sm.sT;
    int cntBefore = sm.sCum - sm.u.hist[T1];   // keys strictly below bin T1
    __syncthreads();                           // all reads done before reuse

    // --- level 2: histogram of bin-T1 keys over bits [40:52) ---
    for (int i = tid; i < NBINS; i += 1024) sm.u.hist[i] = 0;
    if (tid == 0) sm.sSel = 0;
    __syncthreads();
    for (int i = tid; i < cnt; i += 1024) {
        unsigned long long key = g_ckey[b][i];
        if ((int)(key >> 52) == T1)
            atomicAdd(&sm.u.hist[(int)(key >> 40) & 0xFFF], 1);
    }
    __syncthreads();
    scan_find_bin(sm, target - cntBefore, tid, lane, wid);
    __syncthreads();
    int T2 = sm.sT;
    int S = min(cntBefore + sm.sCum, SELC);    // S ~= target + few collisions

    // --- compact the selected superset ---
    for (int i = tid; i < cnt; i += 1024) {
        unsigned long long key = g_ckey[b][i];
        int b1 = (int)(key >> 52);
        if (b1 < T1 || (b1 == T1 && ((int)(key >> 40) & 0xFFF) <= T2)) {
            int pos = atomicAdd(&sm.sSel, 1);
            if (pos < SELC) sm.sel[pos] = key;
        }
    }
    __syncthreads();
    if (tid >= S) sm.sel[tid] = ~0ULL;        // pad to M=1024
    __syncthreads();

    // --- bitonic sort of M=1024, barrier-lean:
    //     stages k=2..32 fully in registers (intra-warp shuffles);
    //     stages k>=64: smem passes for j>=32, 5-shuffle register tail.
    //     Same comparison network as a plain bitonic sort -> identical order.
    {
        unsigned long long e = sm.sel[tid];
        #pragma unroll
        for (int k = 2; k <= 32; k <<= 1) {
            #pragma unroll
            for (int j = k >> 1; j > 0; j >>= 1) {
                unsigned long long o = bx(e, j);
                bool takeMin = ((tid & k) == 0) == ((tid & j) == 0);
                e = ((e < o) == takeMin) ? e : o;
            }
        }
        sm.sel[tid] = e;
        __syncthreads();
        for (int k = 64; k <= 1024; k <<= 1) {
            for (int j = k >> 1; j >= 32; j >>= 1) {
                int ixj = tid ^ j;
                if (ixj > tid) {
                    unsigned long long a = sm.sel[tid], c2 = sm.sel[ixj];
                    bool up = ((tid & k) == 0);
                    if ((a > c2) == up) { sm.sel[tid] = c2; sm.sel[ixj] = a; }
                }
                __syncthreads();
            }
            e = sm.sel[tid];
            #pragma unroll
            for (int j = 16; j > 0; j >>= 1) {
                unsigned long long o = bx(e, j);
                bool takeMin = ((tid & k) == 0) == ((tid & j) == 0);
                e = ((e < o) == takeMin) ? e : o;
            }
            sm.sel[tid] = e;
            __syncthreads();
        }
    }

    int nv = target;
    if (tid == 0) g_nvalid[b] = nv;

    // --- decode junction tid (one thread per junction) ---
    float qx = 0.f, qy = 0.f;
    int myCell = -1;
    const float* rb = raw + (size_t)b * 9 * HWp;
    if (tid < Jp) {
        if (tid < nv) {
            unsigned long long key = sm.sel[tid];
            int p = (int)(key & 0xFFFFFFFFu);
            float offx = sigf(rb[7 * HWp + p]) - 0.5f;
            float offy = sigf(rb[8 * HWp + p]) - 0.5f;
            qx = (float)(p & 255) + offx + 0.5f;
            qy = (float)(p >> 8) + offy + 0.5f;
            myCell = (((int)qy >> 3) << 5) + ((int)qx >> 3);   // 32x32 cells of 8px
        }
        g_juncs[b][tid] = make_float2(qx, qy);
    }
    __syncthreads();          // done with sel/hist before reuse

    // --- build CSR cell grid ---
    sm.u.cnt1[tid] = 0;
    __syncthreads();
    if (myCell >= 0) atomicAdd(&sm.u.cnt1[myCell], 1);
    __syncthreads();
    int v = sm.u.cnt1[tid];
    int inc2 = v;
    #pragma unroll
    for (int d = 1; d < 32; d <<= 1) {
        int n = __shfl_up_sync(0xffffffffu, inc2, d);
        if (lane >= d) inc2 += n;
    }
    if (lane == 31) sm.warpsum[wid] = inc2;
    __syncthreads();
    if (wid == 0) {
        int vv = sm.warpsum[lane];
        int i2 = vv;
        #pragma unroll
        for (int d = 1; d < 32; d <<= 1) {
            int n = __shfl_up_sync(0xffffffffu, i2, d);
            if (lane >= d) i2 += n;
        }
        sm.warpsum[lane] = i2 - vv;
    }
    __syncthreads();
    int excl = sm.warpsum[wid] + inc2 - v;
    g_cellStart[b][tid] = excl;
    if (tid == 1023) g_cellStart[b][1024] = excl + v;   // == nv
    __syncthreads();
    sm.u.cnt1[tid] = excl;     // fill cursors
    __syncthreads();
    if (myCell >= 0) {
        int pos = atomicAdd(&sm.u.cnt1[myCell], 1);
        g_gpack[b][pos] = make_float4(qx, qy, __int_as_float(tid), 0.f);
    }
}

// ---------------------------------------------------------------------------
// Pruned nearest-junction search with row-contiguous CSR scan: cells
// cx0..cx1 of one row are adjacent in CSR order, so one contiguous range per
// row — same elements, same ascending order as per-cell loops. Packed float4
// (x, y, idx_bits) = one LDG.128 per junction. (d, idx) lexicographic min
// reproduces the reference argmin first-index tie-break exactly.
// ---------------------------------------------------------------------------
__device__ __forceinline__ void nearest(const float4* __restrict__ gp,
                                        const int* __restrict__ cs,
                                        float ex, float ey,
                                        float& bd, int& bi) {
    int cx0 = ((int)fmaxf(ex - RADp, 0.0f)) >> 3;
    int cx1 = ((int)fminf(ex + RADp, 255.0f)) >> 3;
    int cy0 = ((int)fmaxf(ey - RADp, 0.0f)) >> 3;
    int cy1 = ((int)fminf(ey + RADp, 255.0f)) >> 3;
    for (int cy = cy0; cy <= cy1; cy++) {
        int s = __ldg(&cs[(cy << 5) + cx0]);
        int e = __ldg(&cs[(cy << 5) + cx1 + 1]);
        for (int k = s; k < e; k++) {
            float4 q = __ldg(&gp[k]);
            int idx  = __float_as_int(q.z);
            float dx = ex - q.x, dy = ey - q.y;
            float d = fmaf(dy, dy, dx * dx);
            if (d < bd || (d == bd && idx < bi)) { bd = d; bi = idx; }
        }
    }
}

// ---------------------------------------------------------------------------
// Scatter one matched line. First toucher (atomicAdd returns 0) also writes
// lines_adj[g] — value depends only on g, so winner identity is irrelevant.
// ---------------------------------------------------------------------------
__device__ __forceinline__ void scatter(int b, float l0, float l1, float l2, float l3,
                                        float bd1, int bi1, float bd2, int bi2,
                                        float4* __restrict__ lines,
                                        float* __restrict__ counts,
                                        float* __restrict__ support) {
    if (bd1 < J2Lp && bd2 < J2Lp && bi1 != bi2) {
        int imin = min(bi1, bi2), imax = max(bi1, bi2);
        int g = b * JJp + imin * Jp + imax;
        float old = atomicAdd(&counts[g], 1.0f);
        atomicAdd(&support[(size_t)g * 4 + 0], l0);
        atomicAdd(&support[(size_t)g * 4 + 1], l1);
        atomicAdd(&support[(size_t)g * 4 + 2], l2);
        atomicAdd(&support[(size_t)g * 4 + 3], l3);
        if (old == 0.0f) {
            float2 A  = g_juncs[b][imin];
            float2 Bq = g_juncs[b][imax];
            lines[g] = make_float4(A.x, A.y, Bq.x, Bq.y);
        }
    }
}

// ---------------------------------------------------------------------------
// K3: decode two pixels per thread with interleaved (independent) trig chains
// for ILP, then the four pruned nearest searches, then scatters.
// ---------------------------------------------------------------------------
__global__ void __launch_bounds__(256) k_match(const float* __restrict__ raw,
                                               float4* __restrict__ lines,
                                               float* __restrict__ counts,
                                               float* __restrict__ support) {
    int b = blockIdx.y;
    if (b == 0 && blockIdx.x == 0 && threadIdx.x == 0) {
        g_ccnt[0] = 0; g_ccnt[1] = 0;    // reset for next replay (topk consumed it)
    }
    const float* rb = raw + (size_t)b * 9 * HWp;
    const float4* gp = g_gpack[b];
    const int* cs = g_cellStart[b];
    int pA = blockIdx.x * 512 + threadIdx.x;
    int pB = pA + 256;

    // --- interleaved decode of both pixels (independent chains -> ILP) ---
    float a0 = rb[pA],           b0 = rb[pB];
    float a1 = rb[HWp + pA],     b1 = rb[HWp + pB];
    float a2 = rb[2 * HWp + pA], b2 = rb[2 * HWp + pB];
    float a3 = rb[3 * HWp + pA], b3 = rb[3 * HWp + pB];

    float amd0 = sigf(a0), bmd0 = sigf(b0);
    float amd1 = sigf(a1), bmd1 = sigf(b1);
    float amd2 = sigf(a2), bmd2 = sigf(b2);
    float ad   = sigf(a3), bdd  = sigf(b3);

    float ath = (amd0 - 0.5f) * 6.28318530717958647692f;
    float bth = (bmd0 - 0.5f) * 6.28318530717958647692f;
    float acs, ass, bcs, bss;
    sincosf(ath, &ass, &acs);
    sincosf(bth, &bss, &bcs);
    float ayst = tanf(amd1 * 1.57079632679489661923f);
    float byst = tanf(bmd1 * 1.57079632679489661923f);
    float ayed = tanf(-amd2 * 1.57079632679489661923f);
    float byed = tanf(-bmd2 * 1.57079632679489661923f);
    float ads = ad * SCALEp, bds = bdd * SCALEp;

    float ax0 = (float)(pA & 255), ay0 = (float)(pA >> 8);
    float bx0 = (float)(pB & 255), by0 = (float)(pB >> 8);

    float al0 = fminf(fmaxf((acs - ass * ayst) * ads + ax0, 0.0f), 255.0f);
    float al1 = fminf(fmaxf((ass + acs * ayst) * ads + ay0, 0.0f), 255.0f);
    float al2 = fminf(fmaxf((acs - ass * ayed) * ads + ax0, 0.0f), 255.0f);
    float al3 = fminf(fmaxf((ass + acs * ayed) * ads + ay0, 0.0f), 255.0f);
    float bl0 = fminf(fmaxf((bcs - bss * byst) * bds + bx0, 0.0f), 255.0f);
    float bl1 = fminf(fmaxf((bss + bcs * byst) * bds + by0, 0.0f), 255.0f);
    float bl2 = fminf(fmaxf((bcs - bss * byed) * bds + bx0, 0.0f), 255.0f);
    float bl3 = fminf(fmaxf((bss + bcs * byed) * bds + by0, 0.0f), 255.0f);

    // --- nearest searches ---
    float abd1 = 1e30f, abd2 = 1e30f, bbd1 = 1e30f, bbd2 = 1e30f;
    int   abi1 = Jp, abi2 = Jp, bbi1 = Jp, bbi2 = Jp;
    nearest(gp, cs, al0, al1, abd1, abi1);
    nearest(gp, cs, al2, al3, abd2, abi2);
    nearest(gp, cs, bl0, bl1, bbd1, bbi1);
    nearest(gp, cs, bl2, bl3, bbd2, bbi2);

    scatter(b, al0, al1, al2, al3, abd1, abi1, abd2, abi2, lines, counts, support);
    scatter(b, bl0, bl1, bl2, bl3, bbd1, bbi1, bbd2, bbi2, lines, counts, support);
}

// ---------------------------------------------------------------------------
// Launch. Output layout: lines_adj [B*JJ*4] | counts [B*JJ] | support [B*JJ*4]
// ---------------------------------------------------------------------------
extern "C" void kernel_launch(void* const* d_in, const int* in_sizes, int n_in,
                              void* d_out, int out_size) {
    const float* raw = (const float*)d_in[0];
    float* out = (float*)d_out;
    float* counts  = out + (size_t)Bp * JJp * 4;
    float* support = counts + (size_t)Bp * JJp;

    dim3 gcand(TILES + ZBLKC, Bp);
    k_cand_zero<<<gcand, 1024>>>(raw, (float4*)out);  // zeroes 1/3 of output
    k_topk<<<Bp + ZBLKT, 1024>>>(raw, (float4*)out);  // zeroes the other 2/3
    dim3 gmatch(HWp / 512, Bp);
    k_match<<<gmatch, 256>>>(raw, (float4*)out, counts, support);
}